// round 1
// baseline (speedup 1.0000x reference)
#include <cuda_runtime.h>
#include <cuda_bf16.h>
#include <math.h>

// Problem constants (fixed shapes)
#define BATCH 4
#define NSEQ 1024
#define DIM 1024
#define HEADS 16
#define DHEAD 64
#define INNER 1024
#define SCALE 0.125f  // 64^-0.5

// ---------------- scratch (device globals; allocation-free) ----------------
__device__ float g_q[(long long)BATCH * NSEQ * INNER];          // 16 MB  [b, i, h*64+d]
__device__ float g_kv[(long long)BATCH * NSEQ * 2 * INNER];     // 32 MB  [b, j, (k|v) h*64+d]
__device__ float g_dots[(long long)BATCH * HEADS * NSEQ * NSEQ];// 256 MB [b, h, i, j]
__device__ float g_attn[(long long)BATCH * HEADS * NSEQ * NSEQ];// 256 MB [b, g, i, j]
__device__ float g_mid[(long long)BATCH * NSEQ * INNER];        // 16 MB  [b, i, g*64+d]

// ---------------- generic NN GEMM: C = alpha*A@B (+bias) -------------------
// Tiles 64x64, BK=16, 256 threads, 4x4 per thread. All dims divide evenly.
#define BM 64
#define BN 64
#define BK 16

__global__ void gemm_nn(const float* __restrict__ A, const float* __restrict__ B,
                        float* __restrict__ C, const float* __restrict__ bias,
                        int K, int lda, int ldb, int ldc, float alpha) {
    __shared__ float As[BK][BM + 1];
    __shared__ float Bs[BK][BN + 1];
    const int bm = blockIdx.y * BM;
    const int bn = blockIdx.x * BN;
    const int tid = threadIdx.x;
    const int tx = tid & 15, ty = tid >> 4;
    float acc[4][4] = {};

    for (int k0 = 0; k0 < K; k0 += BK) {
        #pragma unroll
        for (int t = 0; t < (BM * BK) / 256; t++) {
            int idx = tid + t * 256;
            int r = idx / BK, c = idx % BK;
            As[c][r] = A[(long long)(bm + r) * lda + k0 + c];
        }
        #pragma unroll
        for (int t = 0; t < (BK * BN) / 256; t++) {
            int idx = tid + t * 256;
            int r = idx / BN, c = idx % BN;
            Bs[r][c] = B[(long long)(k0 + r) * ldb + bn + c];
        }
        __syncthreads();
        #pragma unroll
        for (int kk = 0; kk < BK; kk++) {
            float a[4], bq[4];
            #pragma unroll
            for (int i = 0; i < 4; i++) a[i] = As[kk][ty * 4 + i];
            #pragma unroll
            for (int j = 0; j < 4; j++) bq[j] = Bs[kk][tx * 4 + j];
            #pragma unroll
            for (int i = 0; i < 4; i++)
                #pragma unroll
                for (int j = 0; j < 4; j++) acc[i][j] += a[i] * bq[j];
        }
        __syncthreads();
    }
    #pragma unroll
    for (int i = 0; i < 4; i++) {
        long long row = bm + ty * 4 + i;
        #pragma unroll
        for (int j = 0; j < 4; j++) {
            int col = bn + tx * 4 + j;
            float v = acc[i][j] * alpha;
            if (bias) v += bias[col];
            C[row * ldc + col] = v;
        }
    }
}

// ---------------- dots = SCALE * q @ k^T, batched over (b,h) ---------------
// Per batch z=(b*16+h): A = q rows (lda=1024, col offset h*64), B = k rows
// (ldb=2048, offset h*64), K=64 fully staged in smem. C tile 64x64.
__global__ void dots_kernel(const float* __restrict__ q, const float* __restrict__ kv,
                            float* __restrict__ dots) {
    __shared__ float As[64][65];  // As[d][i]
    __shared__ float Bs[64][65];  // Bs[d][j]
    const int z = blockIdx.z;
    const int b = z >> 4, h = z & 15;
    const float* A = q  + (long long)b * NSEQ * INNER     + h * DHEAD;
    const float* B = kv + (long long)b * NSEQ * 2 * INNER + h * DHEAD;  // k half
    float* C = dots + (long long)z * NSEQ * NSEQ;
    const int bm = blockIdx.y * 64;
    const int bn = blockIdx.x * 64;
    const int tid = threadIdx.x;
    const int tx = tid & 15, ty = tid >> 4;

    #pragma unroll
    for (int t = 0; t < 16; t++) {
        int idx = tid + t * 256;
        int r = idx >> 6, d = idx & 63;
        As[d][r] = A[(long long)(bm + r) * INNER + d];
        Bs[d][r] = B[(long long)(bn + r) * (2 * INNER) + d];
    }
    __syncthreads();

    float acc[4][4] = {};
    #pragma unroll 8
    for (int k = 0; k < 64; k++) {
        float a[4], bq[4];
        #pragma unroll
        for (int i = 0; i < 4; i++) a[i] = As[k][ty * 4 + i];
        #pragma unroll
        for (int j = 0; j < 4; j++) bq[j] = Bs[k][tx * 4 + j];
        #pragma unroll
        for (int i = 0; i < 4; i++)
            #pragma unroll
            for (int j = 0; j < 4; j++) acc[i][j] += a[i] * bq[j];
    }
    #pragma unroll
    for (int i = 0; i < 4; i++) {
        long long row = bm + ty * 4 + i;
        #pragma unroll
        for (int j = 0; j < 4; j++)
            C[row * NSEQ + (bn + tx * 4 + j)] = acc[i][j] * SCALE;
    }
}

// ------------- fused mix_pre -> softmax -> mix_post per (b, i) --------------
// One block per (i, b). smem: s_in[16][1024], s_mix[16][1024] = 128 KB dynamic.
__global__ void mix_softmax_mix(const float* __restrict__ dots, float* __restrict__ attn,
                                const float* __restrict__ pre, const float* __restrict__ post) {
    extern __shared__ float smem[];
    float* s_in  = smem;               // [16][1024]
    float* s_mix = smem + 16 * 1024;   // [16][1024]
    __shared__ float spre[256], spost[256];

    const int i = blockIdx.x, b = blockIdx.y;
    const int tid = threadIdx.x;  // 256 threads
    spre[tid] = pre[tid];
    spost[tid] = post[tid];

    const long long base = (long long)b * HEADS * NSEQ * NSEQ + (long long)i * NSEQ;
    #pragma unroll
    for (int h = 0; h < 16; h++)
        for (int j = tid; j < NSEQ; j += 256)
            s_in[h * 1024 + j] = dots[base + (long long)h * NSEQ * NSEQ + j];
    __syncthreads();

    // mixed[g][j] = sum_h s_in[h][j] * pre[h][g]
    for (int j = tid; j < NSEQ; j += 256) {
        float in[16];
        #pragma unroll
        for (int h = 0; h < 16; h++) in[h] = s_in[h * 1024 + j];
        #pragma unroll
        for (int g = 0; g < 16; g++) {
            float s = 0.f;
            #pragma unroll
            for (int h = 0; h < 16; h++) s += in[h] * spre[h * 16 + g];
            s_mix[g * 1024 + j] = s;
        }
    }
    __syncthreads();

    // softmax over j for each g; warp w handles g = w, w+8
    const int warp = tid >> 5, lane = tid & 31;
    for (int g = warp; g < 16; g += 8) {
        float m = -INFINITY;
        for (int j = lane; j < NSEQ; j += 32) m = fmaxf(m, s_mix[g * 1024 + j]);
        #pragma unroll
        for (int o = 16; o; o >>= 1) m = fmaxf(m, __shfl_xor_sync(0xFFFFFFFFu, m, o));
        float s = 0.f;
        for (int j = lane; j < NSEQ; j += 32) {
            float e = __expf(s_mix[g * 1024 + j] - m);
            s_mix[g * 1024 + j] = e;
            s += e;
        }
        #pragma unroll
        for (int o = 16; o; o >>= 1) s += __shfl_xor_sync(0xFFFFFFFFu, s, o);
        float inv = 1.f / s;
        for (int j = lane; j < NSEQ; j += 32) s_mix[g * 1024 + j] *= inv;
    }
    __syncthreads();

    // attn[g'][j] = sum_g s_mix[g][j] * post[g][g']
    for (int j = tid; j < NSEQ; j += 256) {
        float in[16];
        #pragma unroll
        for (int g = 0; g < 16; g++) in[g] = s_mix[g * 1024 + j];
        #pragma unroll
        for (int gp = 0; gp < 16; gp++) {
            float s = 0.f;
            #pragma unroll
            for (int g = 0; g < 16; g++) s += in[g] * spost[g * 16 + gp];
            attn[base + (long long)gp * NSEQ * NSEQ + j] = s;
        }
    }
}

// ---------------- out = attn @ v, batched over (b,g) -----------------------
__global__ void av_kernel(const float* __restrict__ attn, const float* __restrict__ kv,
                          float* __restrict__ mid) {
    __shared__ float As[BK][BM + 1];
    __shared__ float Bs[BK][BN + 1];
    const int z = blockIdx.z;
    const int b = z >> 4, g = z & 15;
    const float* A = attn + (long long)z * NSEQ * NSEQ;                       // lda=1024
    const float* B = kv + (long long)b * NSEQ * 2 * INNER + INNER + g * DHEAD;// ldb=2048 (v)
    float* C = mid + (long long)b * NSEQ * INNER + g * DHEAD;                 // ldc=1024
    const int bm = blockIdx.y * BM;
    const int tid = threadIdx.x;
    const int tx = tid & 15, ty = tid >> 4;
    float acc[4][4] = {};

    for (int k0 = 0; k0 < NSEQ; k0 += BK) {
        #pragma unroll
        for (int t = 0; t < (BM * BK) / 256; t++) {
            int idx = tid + t * 256;
            int r = idx / BK, c = idx % BK;
            As[c][r] = A[(long long)(bm + r) * NSEQ + k0 + c];
        }
        // B tile: 16 rows x 64 cols (N==BN==64, only one N block)
        {
            int r = tid >> 6, c = tid & 63;        // 4 rows per pass
            #pragma unroll
            for (int t = 0; t < 4; t++)
                Bs[r + t * 4][c] = B[(long long)(k0 + r + t * 4) * (2 * INNER) + c];
        }
        __syncthreads();
        #pragma unroll
        for (int kk = 0; kk < BK; kk++) {
            float a[4], bq[4];
            #pragma unroll
            for (int i = 0; i < 4; i++) a[i] = As[kk][ty * 4 + i];
            #pragma unroll
            for (int j = 0; j < 4; j++) bq[j] = Bs[kk][tx * 4 + j];
            #pragma unroll
            for (int i = 0; i < 4; i++)
                #pragma unroll
                for (int j = 0; j < 4; j++) acc[i][j] += a[i] * bq[j];
        }
        __syncthreads();
    }
    #pragma unroll
    for (int i = 0; i < 4; i++) {
        long long row = bm + ty * 4 + i;
        #pragma unroll
        for (int j = 0; j < 4; j++)
            C[row * INNER + (tx * 4 + j)] = acc[i][j];
    }
}

// ---------------------------------------------------------------------------
extern "C" void kernel_launch(void* const* d_in, const int* in_sizes, int n_in,
                              void* d_out, int out_size) {
    const float* x       = (const float*)d_in[0];
    const float* Wq      = (const float*)d_in[1];
    const float* Wkv     = (const float*)d_in[2];
    const float* mix_pre = (const float*)d_in[3];
    const float* mix_post= (const float*)d_in[4];
    const float* Wo      = (const float*)d_in[5];
    const float* bo      = (const float*)d_in[6];
    float* out = (float*)d_out;

    float *q, *kv, *dots, *attn, *mid;
    cudaGetSymbolAddress((void**)&q,    g_q);
    cudaGetSymbolAddress((void**)&kv,   g_kv);
    cudaGetSymbolAddress((void**)&dots, g_dots);
    cudaGetSymbolAddress((void**)&attn, g_attn);
    cudaGetSymbolAddress((void**)&mid,  g_mid);

    const int M = BATCH * NSEQ;  // 4096

    // 1) q = x @ Wq    [4096,1024] = [4096,1024]@[1024,1024]
    gemm_nn<<<dim3(INNER / BN, M / BM), 256>>>(x, Wq, q, nullptr,
                                               DIM, DIM, INNER, INNER, 1.f);
    // 2) kv = x @ Wkv  [4096,2048]
    gemm_nn<<<dim3(2 * INNER / BN, M / BM), 256>>>(x, Wkv, kv, nullptr,
                                                   DIM, DIM, 2 * INNER, 2 * INNER, 1.f);
    // 3) dots = SCALE * q k^T, batched over 64 (b,h)
    dots_kernel<<<dim3(NSEQ / 64, NSEQ / 64, BATCH * HEADS), 256>>>(q, kv, dots);

    // 4) fused mix_pre -> softmax -> mix_post
    static const int MIX_SMEM = 2 * 16 * 1024 * sizeof(float);  // 128 KB
    cudaFuncSetAttribute(mix_softmax_mix, cudaFuncAttributeMaxDynamicSharedMemorySize, MIX_SMEM);
    mix_softmax_mix<<<dim3(NSEQ, BATCH), 256, MIX_SMEM>>>(dots, attn, mix_pre, mix_post);

    // 5) mid = attn @ v, batched over 64 (b,g)
    av_kernel<<<dim3(1, NSEQ / BM, BATCH * HEADS), 256>>>(attn, kv, mid);

    // 6) out = mid @ Wo + bo
    gemm_nn<<<dim3(DIM / BN, M / BM), 256>>>(mid, Wo, out, bo,
                                             INNER, INNER, DIM, DIM, 1.f);
}

// round 3
// speedup vs baseline: 1.3461x; 1.3461x over previous
#include <cuda_runtime.h>
#include <cuda_bf16.h>
#include <mma.h>
#include <math.h>

using namespace nvcuda;

// Problem constants (fixed shapes)
#define BATCH 4
#define NSEQ 1024
#define DIM 1024
#define HEADS 16
#define DHEAD 64
#define INNER 1024
#define SCALE 0.125f  // 64^-0.5

// ---------------- scratch (device globals; allocation-free) ----------------
__device__ float g_q[(long long)BATCH * NSEQ * INNER];          // 16 MB
__device__ float g_kv[(long long)BATCH * NSEQ * 2 * INNER];     // 32 MB
__device__ float g_dots[(long long)BATCH * HEADS * NSEQ * NSEQ];// 256 MB
__device__ float g_attn[(long long)BATCH * HEADS * NSEQ * NSEQ];// 256 MB
__device__ float g_mid[(long long)BATCH * NSEQ * INNER];        // 16 MB

__device__ __forceinline__ void split_bf16(float x, __nv_bfloat16& h, __nv_bfloat16& l) {
    h = __float2bfloat16(x);
    l = __float2bfloat16(x - __bfloat162float(h));
}

// ---------------------------------------------------------------------------
// Split-bf16 (3-term) tensor-core GEMM:  C = (a_scale*A) @ op(B) (+bias)
//   A = A_hi + A_lo, B = B_hi + B_lo (bf16 each);
//   acc += A_hi B_hi + A_hi B_lo + A_lo B_hi  (fp32 accumulate)
//   BT=false: B is [K,N] row-major.  BT=true: B is [N,K] row-major (B^T).
// Batched over blockIdx.z (z = zb*16 + zh) with per-operand strides.
// ---------------------------------------------------------------------------
template<int BM, int BN, int BK, int WM, int WN, bool BT>
__global__ void gemm_bf16x3(const float* __restrict__ A, const float* __restrict__ B,
                            float* __restrict__ C, const float* __restrict__ bias,
                            int K, int lda, int ldb, int ldc,
                            long long sa_b, long long sa_h,
                            long long sb_b, long long sb_h,
                            long long sc_b, long long sc_h,
                            float a_scale)
{
    constexpr int WARPS_M = BM / WM;
    constexpr int WARPS_N = BN / WN;
    constexpr int NT = WARPS_M * WARPS_N * 32;
    constexpr int BKP = BK + 4;       // bf16 elems, keeps bf162 alignment (even)
    constexpr int BNP = BN + 4;
    constexpr int BNP_F = BN + 4;     // float padding for bias tile
    constexpr int FM = WM / 16;
    constexpr int FN = WN / 16;

    __shared__ __nv_bfloat16 sA_hi[BM * BKP];
    __shared__ __nv_bfloat16 sA_lo[BM * BKP];
    __shared__ __nv_bfloat16 sB_hi[BT ? (BN * BKP) : (BK * BNP)];
    __shared__ __nv_bfloat16 sB_lo[BT ? (BN * BKP) : (BK * BNP)];
    __shared__ float sbias[16 * BNP_F];

    const int z = blockIdx.z;
    const int zb = z >> 4, zh = z & 15;
    A += zb * sa_b + zh * sa_h;
    B += zb * sb_b + zh * sb_h;
    C += zb * sc_b + zh * sc_h;

    const int bm = blockIdx.y * BM;
    const int bn = blockIdx.x * BN;
    const int tid = threadIdx.x;
    const int warp = tid >> 5;
    const int wm = (warp / WARPS_N) * WM;
    const int wn = (warp % WARPS_N) * WN;

    wmma::fragment<wmma::accumulator, 16, 16, 16, float> acc[FM][FN];
    if (bias) {
        for (int idx = tid; idx < 16 * BN; idx += NT) {
            int r = idx / BN, c = idx % BN;
            sbias[r * BNP_F + c] = bias[bn + c];
        }
        __syncthreads();
        #pragma unroll
        for (int i = 0; i < FM; i++)
            #pragma unroll
            for (int j = 0; j < FN; j++)
                wmma::load_matrix_sync(acc[i][j], &sbias[wn + j * 16], BNP_F, wmma::mem_row_major);
        __syncthreads();
    } else {
        #pragma unroll
        for (int i = 0; i < FM; i++)
            #pragma unroll
            for (int j = 0; j < FN; j++)
                wmma::fill_fragment(acc[i][j], 0.f);
    }

    for (int k0 = 0; k0 < K; k0 += BK) {
        // ---- stage A tile [BM][BK], split into hi/lo ----
        #pragma unroll
        for (int idx = tid * 4; idx < BM * BK; idx += NT * 4) {
            int r = idx / BK, c = idx % BK;
            float4 v = *reinterpret_cast<const float4*>(
                &A[(long long)(bm + r) * lda + k0 + c]);
            v.x *= a_scale; v.y *= a_scale; v.z *= a_scale; v.w *= a_scale;
            __nv_bfloat16 h0, l0, h1, l1, h2, l2, h3, l3;
            split_bf16(v.x, h0, l0); split_bf16(v.y, h1, l1);
            split_bf16(v.z, h2, l2); split_bf16(v.w, h3, l3);
            int o = r * BKP + c;
            *reinterpret_cast<__nv_bfloat162*>(&sA_hi[o])     = __nv_bfloat162(h0, h1);
            *reinterpret_cast<__nv_bfloat162*>(&sA_hi[o + 2]) = __nv_bfloat162(h2, h3);
            *reinterpret_cast<__nv_bfloat162*>(&sA_lo[o])     = __nv_bfloat162(l0, l1);
            *reinterpret_cast<__nv_bfloat162*>(&sA_lo[o + 2]) = __nv_bfloat162(l2, l3);
        }
        // ---- stage B tile, split into hi/lo ----
        if (BT) {
            #pragma unroll
            for (int idx = tid * 4; idx < BN * BK; idx += NT * 4) {
                int r = idx / BK, c = idx % BK;
                const float4 v = *reinterpret_cast<const float4*>(
                    &B[(long long)(bn + r) * ldb + k0 + c]);
                __nv_bfloat16 h0, l0, h1, l1, h2, l2, h3, l3;
                split_bf16(v.x, h0, l0); split_bf16(v.y, h1, l1);
                split_bf16(v.z, h2, l2); split_bf16(v.w, h3, l3);
                int o = r * BKP + c;
                *reinterpret_cast<__nv_bfloat162*>(&sB_hi[o])     = __nv_bfloat162(h0, h1);
                *reinterpret_cast<__nv_bfloat162*>(&sB_hi[o + 2]) = __nv_bfloat162(h2, h3);
                *reinterpret_cast<__nv_bfloat162*>(&sB_lo[o])     = __nv_bfloat162(l0, l1);
                *reinterpret_cast<__nv_bfloat162*>(&sB_lo[o + 2]) = __nv_bfloat162(l2, l3);
            }
        } else {
            #pragma unroll
            for (int idx = tid * 4; idx < BK * BN; idx += NT * 4) {
                int r = idx / BN, c = idx % BN;
                const float4 v = *reinterpret_cast<const float4*>(
                    &B[(long long)(k0 + r) * ldb + bn + c]);
                __nv_bfloat16 h0, l0, h1, l1, h2, l2, h3, l3;
                split_bf16(v.x, h0, l0); split_bf16(v.y, h1, l1);
                split_bf16(v.z, h2, l2); split_bf16(v.w, h3, l3);
                int o = r * BNP + c;
                *reinterpret_cast<__nv_bfloat162*>(&sB_hi[o])     = __nv_bfloat162(h0, h1);
                *reinterpret_cast<__nv_bfloat162*>(&sB_hi[o + 2]) = __nv_bfloat162(h2, h3);
                *reinterpret_cast<__nv_bfloat162*>(&sB_lo[o])     = __nv_bfloat162(l0, l1);
                *reinterpret_cast<__nv_bfloat162*>(&sB_lo[o + 2]) = __nv_bfloat162(l2, l3);
            }
        }
        __syncthreads();

        #pragma unroll
        for (int kk = 0; kk < BK; kk += 16) {
            wmma::fragment<wmma::matrix_a, 16, 16, 16, __nv_bfloat16, wmma::row_major> fa_hi[FM], fa_lo[FM];
            #pragma unroll
            for (int i = 0; i < FM; i++) {
                wmma::load_matrix_sync(fa_hi[i], &sA_hi[(wm + i * 16) * BKP + kk], BKP);
                wmma::load_matrix_sync(fa_lo[i], &sA_lo[(wm + i * 16) * BKP + kk], BKP);
            }
            #pragma unroll
            for (int j = 0; j < FN; j++) {
                if constexpr (BT) {
                    wmma::fragment<wmma::matrix_b, 16, 16, 16, __nv_bfloat16, wmma::col_major> fb_hi, fb_lo;
                    wmma::load_matrix_sync(fb_hi, &sB_hi[(wn + j * 16) * BKP + kk], BKP);
                    wmma::load_matrix_sync(fb_lo, &sB_lo[(wn + j * 16) * BKP + kk], BKP);
                    #pragma unroll
                    for (int i = 0; i < FM; i++) {
                        wmma::mma_sync(acc[i][j], fa_hi[i], fb_hi, acc[i][j]);
                        wmma::mma_sync(acc[i][j], fa_hi[i], fb_lo, acc[i][j]);
                        wmma::mma_sync(acc[i][j], fa_lo[i], fb_hi, acc[i][j]);
                    }
                } else {
                    wmma::fragment<wmma::matrix_b, 16, 16, 16, __nv_bfloat16, wmma::row_major> fb_hi, fb_lo;
                    wmma::load_matrix_sync(fb_hi, &sB_hi[kk * BNP + wn + j * 16], BNP);
                    wmma::load_matrix_sync(fb_lo, &sB_lo[kk * BNP + wn + j * 16], BNP);
                    #pragma unroll
                    for (int i = 0; i < FM; i++) {
                        wmma::mma_sync(acc[i][j], fa_hi[i], fb_hi, acc[i][j]);
                        wmma::mma_sync(acc[i][j], fa_hi[i], fb_lo, acc[i][j]);
                        wmma::mma_sync(acc[i][j], fa_lo[i], fb_hi, acc[i][j]);
                    }
                }
            }
        }
        __syncthreads();
    }

    #pragma unroll
    for (int i = 0; i < FM; i++)
        #pragma unroll
        for (int j = 0; j < FN; j++)
            wmma::store_matrix_sync(&C[(long long)(bm + wm + i * 16) * ldc + bn + wn + j * 16],
                                    acc[i][j], ldc, wmma::mem_row_major);
}

// ------------- fused mix_pre -> softmax -> mix_post per (b, i) --------------
__global__ void mix_softmax_mix(const float* __restrict__ dots, float* __restrict__ attn,
                                const float* __restrict__ pre, const float* __restrict__ post) {
    extern __shared__ float s_mix[];   // [16][1024] = 64 KB
    __shared__ float spre[256], spost[256];

    const int i = blockIdx.x, b = blockIdx.y;
    const int tid = threadIdx.x;
    spre[tid] = pre[tid];
    spost[tid] = post[tid];
    __syncthreads();

    const long long base = (long long)b * HEADS * NSEQ * NSEQ + (long long)i * NSEQ;

    float in[16][4];
    #pragma unroll
    for (int h = 0; h < 16; h++)
        #pragma unroll
        for (int t = 0; t < 4; t++)
            in[h][t] = dots[base + (long long)h * NSEQ * NSEQ + tid + t * 256];

    #pragma unroll
    for (int g = 0; g < 16; g++) {
        #pragma unroll
        for (int t = 0; t < 4; t++) {
            float s = 0.f;
            #pragma unroll
            for (int h = 0; h < 16; h++) s += in[h][t] * spre[h * 16 + g];
            s_mix[g * 1024 + tid + t * 256] = s;
        }
    }
    __syncthreads();

    const int warp = tid >> 5, lane = tid & 31;
    #pragma unroll
    for (int g = warp; g < 16; g += 8) {
        float m = -INFINITY;
        for (int j = lane; j < NSEQ; j += 32) m = fmaxf(m, s_mix[g * 1024 + j]);
        #pragma unroll
        for (int o = 16; o; o >>= 1) m = fmaxf(m, __shfl_xor_sync(0xFFFFFFFFu, m, o));
        float s = 0.f;
        for (int j = lane; j < NSEQ; j += 32) {
            float e = __expf(s_mix[g * 1024 + j] - m);
            s_mix[g * 1024 + j] = e;
            s += e;
        }
        #pragma unroll
        for (int o = 16; o; o >>= 1) s += __shfl_xor_sync(0xFFFFFFFFu, s, o);
        float inv = 1.f / s;
        for (int j = lane; j < NSEQ; j += 32) s_mix[g * 1024 + j] *= inv;
    }
    __syncthreads();

    #pragma unroll
    for (int g = 0; g < 16; g++)
        #pragma unroll
        for (int t = 0; t < 4; t++)
            in[g][t] = s_mix[g * 1024 + tid + t * 256];

    #pragma unroll
    for (int gp = 0; gp < 16; gp++) {
        #pragma unroll
        for (int t = 0; t < 4; t++) {
            float s = 0.f;
            #pragma unroll
            for (int g = 0; g < 16; g++) s += in[g][t] * spost[g * 16 + gp];
            attn[base + (long long)gp * NSEQ * NSEQ + tid + t * 256] = s;
        }
    }
}

// ---------------------------------------------------------------------------
extern "C" void kernel_launch(void* const* d_in, const int* in_sizes, int n_in,
                              void* d_out, int out_size) {
    const float* x        = (const float*)d_in[0];
    const float* Wq       = (const float*)d_in[1];
    const float* Wkv      = (const float*)d_in[2];
    const float* mix_pre  = (const float*)d_in[3];
    const float* mix_post = (const float*)d_in[4];
    const float* Wo       = (const float*)d_in[5];
    const float* bo       = (const float*)d_in[6];
    float* out = (float*)d_out;

    float *q, *kv, *dots, *attn, *mid;
    cudaGetSymbolAddress((void**)&q,    g_q);
    cudaGetSymbolAddress((void**)&kv,   g_kv);
    cudaGetSymbolAddress((void**)&dots, g_dots);
    cudaGetSymbolAddress((void**)&attn, g_attn);
    cudaGetSymbolAddress((void**)&mid,  g_mid);

    // 1) q = x @ Wq   [4096,1024]
    gemm_bf16x3<128,128,32,64,32,false><<<dim3(8, 32, 1), 256>>>(
        x, Wq, q, nullptr, DIM, DIM, INNER, INNER,
        0, 0, 0, 0, 0, 0, 1.f);

    // 2) kv = x @ Wkv [4096,2048]
    gemm_bf16x3<128,128,32,64,32,false><<<dim3(16, 32, 1), 256>>>(
        x, Wkv, kv, nullptr, DIM, DIM, 2 * INNER, 2 * INNER,
        0, 0, 0, 0, 0, 0, 1.f);

    // 3) dots = (SCALE*q) @ k^T, batched over z=(b,h)
    gemm_bf16x3<128,128,32,64,32,true><<<dim3(8, 8, BATCH * HEADS), 256>>>(
        q, kv, dots, nullptr, DHEAD, INNER, 2 * INNER, NSEQ,
        (long long)NSEQ * INNER, DHEAD,
        (long long)NSEQ * 2 * INNER, DHEAD,
        (long long)HEADS * NSEQ * NSEQ, (long long)NSEQ * NSEQ,
        SCALE);

    // 4) fused mix_pre -> softmax -> mix_post
    static const int MIX_SMEM = 16 * 1024 * sizeof(float);  // 64 KB
    cudaFuncSetAttribute(mix_softmax_mix, cudaFuncAttributeMaxDynamicSharedMemorySize, MIX_SMEM);
    mix_softmax_mix<<<dim3(NSEQ, BATCH), 256, MIX_SMEM>>>(dots, attn, mix_pre, mix_post);

    // 5) mid = attn @ v, batched over z=(b,g)
    gemm_bf16x3<128,64,32,64,32,false><<<dim3(1, 8, BATCH * HEADS), 128>>>(
        attn, kv + INNER, mid, nullptr, NSEQ, NSEQ, 2 * INNER, INNER,
        (long long)HEADS * NSEQ * NSEQ, (long long)NSEQ * NSEQ,
        (long long)NSEQ * 2 * INNER, DHEAD,
        (long long)NSEQ * INNER, DHEAD,
        1.f);

    // 6) out = mid @ Wo + bo   [4096,1024]
    gemm_bf16x3<128,128,32,64,32,false><<<dim3(8, 32, 1), 256>>>(
        mid, Wo, out, bo, INNER, INNER, DIM, DIM,
        0, 0, 0, 0, 0, 0, 1.f);
}

// round 5
// speedup vs baseline: 3.0737x; 2.2833x over previous
#include <cuda_runtime.h>
#include <cuda_bf16.h>
#include <mma.h>
#include <math.h>
#include <cstdint>

using namespace nvcuda;

#define BATCH 4
#define NSEQ 1024
#define DIM 1024
#define HEADS 16
#define DHEAD 64
#define INNER 1024
#define SCALE 0.125f

typedef __nv_bfloat16 bf16;
typedef __nv_bfloat162 bf162;

// ---------------- scratch (device globals; allocation-free) ----------------
#define NELEM_X   ((long long)BATCH * NSEQ * DIM)        // 4M
#define NELEM_WQ  ((long long)DIM * INNER)               // 1M
#define NELEM_WKV ((long long)DIM * 2 * INNER)           // 2M
#define NELEM_WO  ((long long)INNER * DIM)               // 1M
#define NELEM_Q   ((long long)BATCH * NSEQ * INNER)      // 4M
#define NELEM_KV  ((long long)BATCH * NSEQ * 2 * INNER)  // 8M
#define NELEM_ATT ((long long)BATCH * HEADS * NSEQ * NSEQ) // 64M

__device__ bf16 g_xh[NELEM_X],  g_xl[NELEM_X];
__device__ bf16 g_wqh[NELEM_WQ], g_wql[NELEM_WQ];
__device__ bf16 g_wkvh[NELEM_WKV], g_wkvl[NELEM_WKV];
__device__ bf16 g_woh[NELEM_WO], g_wol[NELEM_WO];
__device__ bf16 g_qh[NELEM_Q],  g_ql[NELEM_Q];
__device__ bf16 g_kvh[NELEM_KV], g_kvl[NELEM_KV];
__device__ float g_dots[NELEM_ATT];                      // 256 MB
__device__ bf16 g_ah[NELEM_ATT], g_al[NELEM_ATT];        // 128 MB each
__device__ bf16 g_mh[NELEM_Q],  g_ml[NELEM_Q];

__device__ __forceinline__ void split_bf16(float x, bf16& h, bf16& l) {
    h = __float2bfloat16(x);
    l = __float2bfloat16(x - __bfloat162float(h));
}

__device__ __forceinline__ void cp_async16(void* sdst, const void* gsrc) {
    unsigned sa = (unsigned)__cvta_generic_to_shared(sdst);
    asm volatile("cp.async.cg.shared.global [%0], [%1], 16;\n" :: "r"(sa), "l"(gsrc));
}
__device__ __forceinline__ void cp_commit() { asm volatile("cp.async.commit_group;\n"); }
template<int N>
__device__ __forceinline__ void cp_wait() { asm volatile("cp.async.wait_group %0;\n" :: "n"(N)); }

// ---------------- input split kernel: f32 -> bf16 hi/lo --------------------
__global__ void split_kernel(const float* __restrict__ in, bf16* __restrict__ hi,
                             bf16* __restrict__ lo, int n4) {
    int i = blockIdx.x * blockDim.x + threadIdx.x;
    if (i >= n4) return;
    float4 v = reinterpret_cast<const float4*>(in)[i];
    bf16 h0, l0, h1, l1, h2, l2, h3, l3;
    split_bf16(v.x, h0, l0); split_bf16(v.y, h1, l1);
    split_bf16(v.z, h2, l2); split_bf16(v.w, h3, l3);
    reinterpret_cast<bf162*>(hi)[i * 2]     = __halves2bfloat162(h0, h1);
    reinterpret_cast<bf162*>(hi)[i * 2 + 1] = __halves2bfloat162(h2, h3);
    reinterpret_cast<bf162*>(lo)[i * 2]     = __halves2bfloat162(l0, l1);
    reinterpret_cast<bf162*>(lo)[i * 2 + 1] = __halves2bfloat162(l2, l3);
}

// ---------------------------------------------------------------------------
// Split-bf16 3-term GEMM, pre-split operands, cp.async double-buffered.
//   acc = Ah*Bh + Ah*Bl + Al*Bh  (fp32)
//   BT=false: B[K,N] row-major;  BT=true: B[N,K] row-major (B^T).
//   OUT: 0 = f32 store, 1 = f32 + bias, 2 = split bf16 hi/lo (scaled).
// ---------------------------------------------------------------------------
template<int BM, int BN, int BK, int WM, int WN, bool BT, int OUT>
__global__ void gemm_sp(const bf16* __restrict__ Ah, const bf16* __restrict__ Al,
                        const bf16* __restrict__ Bh, const bf16* __restrict__ Bl,
                        float* __restrict__ Cf, bf16* __restrict__ Ch, bf16* __restrict__ Cl,
                        const float* __restrict__ bias,
                        int K, int lda, int ldb, int ldc,
                        long long sa_b, long long sa_h,
                        long long sb_b, long long sb_h,
                        long long sc_b, long long sc_h,
                        float out_scale)
{
    constexpr int WARPS_M = BM / WM;
    constexpr int WARPS_N = BN / WN;
    constexpr int NWARP = WARPS_M * WARPS_N;
    constexpr int NT = NWARP * 32;
    constexpr int FM = WM / 16;
    constexpr int FN = WN / 16;
    constexpr int BKP = BK + 8;
    constexpr int BNP = BN + 8;
    constexpr int BNPF = BN + 4;
    constexpr int SZA = BM * BKP;                       // elems per stage
    constexpr int SZB = BT ? (BN * BKP) : (BK * BNP);

    extern __shared__ char smem[];
    bf16* sAh = reinterpret_cast<bf16*>(smem);          // [2][SZA]
    bf16* sAl = sAh + 2 * SZA;
    bf16* sBh = sAl + 2 * SZA;                          // [2][SZB]
    bf16* sBl = sBh + 2 * SZB;
    float* sTail = reinterpret_cast<float*>(sBl + 2 * SZB); // bias tile / epilogue scratch

    const int z = blockIdx.z;
    const int zb = z >> 4, zh = z & 15;
    Ah += zb * sa_b + zh * sa_h;  Al += zb * sa_b + zh * sa_h;
    Bh += zb * sb_b + zh * sb_h;  Bl += zb * sb_b + zh * sb_h;
    if (OUT == 2) { Ch += zb * sc_b + zh * sc_h; Cl += zb * sc_b + zh * sc_h; }
    else          { Cf += zb * sc_b + zh * sc_h; }

    const int bm = blockIdx.y * BM;
    const int bn = blockIdx.x * BN;
    const int tid = threadIdx.x;
    const int warp = tid >> 5;
    const int lane = tid & 31;
    const int wm = (warp / WARPS_N) * WM;
    const int wn = (warp % WARPS_N) * WN;

    wmma::fragment<wmma::accumulator, 16, 16, 16, float> acc[FM][FN];
    if (OUT == 1) {
        for (int idx = tid; idx < 16 * BN; idx += NT) {
            int r = idx / BN, c = idx % BN;
            sTail[r * BNPF + c] = bias[bn + c];
        }
        __syncthreads();
        #pragma unroll
        for (int i = 0; i < FM; i++)
            #pragma unroll
            for (int j = 0; j < FN; j++)
                wmma::load_matrix_sync(acc[i][j], &sTail[wn + j * 16], BNPF, wmma::mem_row_major);
        __syncthreads();
    } else {
        #pragma unroll
        for (int i = 0; i < FM; i++)
            #pragma unroll
            for (int j = 0; j < FN; j++)
                wmma::fill_fragment(acc[i][j], 0.f);
    }

    auto load_stage = [&](int st, int k0) {
        constexpr int CHA = (BM * BK) / 8;
        #pragma unroll
        for (int ch = tid; ch < CHA; ch += NT) {
            int r = ch / (BK / 8);
            int c = (ch % (BK / 8)) * 8;
            long long g = (long long)(bm + r) * lda + k0 + c;
            int s = st * SZA + r * BKP + c;
            cp_async16(&sAh[s], &Ah[g]);
            cp_async16(&sAl[s], &Al[g]);
        }
        if (BT) {
            constexpr int CHB = (BN * BK) / 8;
            #pragma unroll
            for (int ch = tid; ch < CHB; ch += NT) {
                int r = ch / (BK / 8);
                int c = (ch % (BK / 8)) * 8;
                long long g = (long long)(bn + r) * ldb + k0 + c;
                int s = st * SZB + r * BKP + c;
                cp_async16(&sBh[s], &Bh[g]);
                cp_async16(&sBl[s], &Bl[g]);
            }
        } else {
            constexpr int CHB = (BK * BN) / 8;
            #pragma unroll
            for (int ch = tid; ch < CHB; ch += NT) {
                int r = ch / (BN / 8);
                int c = (ch % (BN / 8)) * 8;
                long long g = (long long)(k0 + r) * ldb + bn + c;
                int s = st * SZB + r * BNP + c;
                cp_async16(&sBh[s], &Bh[g]);
                cp_async16(&sBl[s], &Bl[g]);
            }
        }
    };

    const int S = K / BK;
    load_stage(0, 0);
    cp_commit();

    for (int s = 0; s < S; s++) {
        if (s + 1 < S) { load_stage((s + 1) & 1, (s + 1) * BK); cp_commit(); cp_wait<1>(); }
        else           { cp_wait<0>(); }
        __syncthreads();

        const int st = s & 1;
        #pragma unroll
        for (int kk = 0; kk < BK; kk += 16) {
            wmma::fragment<wmma::matrix_a, 16, 16, 16, bf16, wmma::row_major> fa_hi[FM], fa_lo[FM];
            #pragma unroll
            for (int i = 0; i < FM; i++) {
                wmma::load_matrix_sync(fa_hi[i], &sAh[st * SZA + (wm + i * 16) * BKP + kk], BKP);
                wmma::load_matrix_sync(fa_lo[i], &sAl[st * SZA + (wm + i * 16) * BKP + kk], BKP);
            }
            #pragma unroll
            for (int j = 0; j < FN; j++) {
                if constexpr (BT) {
                    wmma::fragment<wmma::matrix_b, 16, 16, 16, bf16, wmma::col_major> fb_hi, fb_lo;
                    wmma::load_matrix_sync(fb_hi, &sBh[st * SZB + (wn + j * 16) * BKP + kk], BKP);
                    wmma::load_matrix_sync(fb_lo, &sBl[st * SZB + (wn + j * 16) * BKP + kk], BKP);
                    #pragma unroll
                    for (int i = 0; i < FM; i++) {
                        wmma::mma_sync(acc[i][j], fa_hi[i], fb_hi, acc[i][j]);
                        wmma::mma_sync(acc[i][j], fa_hi[i], fb_lo, acc[i][j]);
                        wmma::mma_sync(acc[i][j], fa_lo[i], fb_hi, acc[i][j]);
                    }
                } else {
                    wmma::fragment<wmma::matrix_b, 16, 16, 16, bf16, wmma::row_major> fb_hi, fb_lo;
                    wmma::load_matrix_sync(fb_hi, &sBh[st * SZB + kk * BNP + wn + j * 16], BNP);
                    wmma::load_matrix_sync(fb_lo, &sBl[st * SZB + kk * BNP + wn + j * 16], BNP);
                    #pragma unroll
                    for (int i = 0; i < FM; i++) {
                        wmma::mma_sync(acc[i][j], fa_hi[i], fb_hi, acc[i][j]);
                        wmma::mma_sync(acc[i][j], fa_hi[i], fb_lo, acc[i][j]);
                        wmma::mma_sync(acc[i][j], fa_lo[i], fb_hi, acc[i][j]);
                    }
                }
            }
        }
        __syncthreads();
    }

    if (OUT <= 1) {
        #pragma unroll
        for (int i = 0; i < FM; i++)
            #pragma unroll
            for (int j = 0; j < FN; j++)
                wmma::store_matrix_sync(&Cf[(long long)(bm + wm + i * 16) * ldc + bn + wn + j * 16],
                                        acc[i][j], ldc, wmma::mem_row_major);
    } else {
        float* scratch = sTail + warp * 16 * 20;
        const int r = lane >> 1;
        const int c0 = (lane & 1) * 8;
        #pragma unroll
        for (int i = 0; i < FM; i++)
            #pragma unroll
            for (int j = 0; j < FN; j++) {
                wmma::store_matrix_sync(scratch, acc[i][j], 20, wmma::mem_row_major);
                __syncwarp();
                long long gr = (long long)(bm + wm + i * 16 + r) * ldc + bn + wn + j * 16 + c0;
                #pragma unroll
                for (int e = 0; e < 8; e += 2) {
                    float v0 = scratch[r * 20 + c0 + e]     * out_scale;
                    float v1 = scratch[r * 20 + c0 + e + 1] * out_scale;
                    bf16 h0, l0, h1, l1;
                    split_bf16(v0, h0, l0); split_bf16(v1, h1, l1);
                    *reinterpret_cast<bf162*>(&Ch[gr + e]) = __halves2bfloat162(h0, h1);
                    *reinterpret_cast<bf162*>(&Cl[gr + e]) = __halves2bfloat162(l0, l1);
                }
                __syncwarp();
            }
    }
}

// ------------- fused mix_pre -> softmax -> mix_post, register-resident ------
// 512 threads, one block per (i,b); each thread owns 2 adjacent j columns.
__global__ void mix_softmax_mix2(const float* __restrict__ dots,
                                 bf16* __restrict__ ah, bf16* __restrict__ al,
                                 const float* __restrict__ pre, const float* __restrict__ post) {
    __shared__ float spre[256], spost[256], sred[16 * 16], sfin[16], sinv[16];
    const int tid = threadIdx.x;
    const int i = blockIdx.x, b = blockIdx.y;
    if (tid < 256) { spre[tid] = pre[tid]; spost[tid] = post[tid]; }
    __syncthreads();

    const long long base = (long long)b * HEADS * NSEQ * NSEQ + (long long)i * NSEQ;
    const int j0 = tid * 2;
    const int warp = tid >> 5, lane = tid & 31;

    float in0[16], in1[16];
    #pragma unroll
    for (int h = 0; h < 16; h++) {
        float2 v = *reinterpret_cast<const float2*>(&dots[base + (long long)h * NSEQ * NSEQ + j0]);
        in0[h] = v.x; in1[h] = v.y;
    }

    float e0[16], e1[16];
    #pragma unroll
    for (int g = 0; g < 16; g++) {
        float m0 = 0.f, m1 = 0.f;
        #pragma unroll
        for (int h = 0; h < 16; h++) {
            float w = spre[h * 16 + g];
            m0 += in0[h] * w; m1 += in1[h] * w;
        }
        e0[g] = m0; e1[g] = m1;
    }

    // block max per g
    #pragma unroll
    for (int g = 0; g < 16; g++) {
        float m = fmaxf(e0[g], e1[g]);
        #pragma unroll
        for (int o = 16; o; o >>= 1) m = fmaxf(m, __shfl_xor_sync(0xFFFFFFFFu, m, o));
        if (lane == 0) sred[g * 16 + warp] = m;
    }
    __syncthreads();
    if (tid < 16) {
        float m = -INFINITY;
        #pragma unroll
        for (int w = 0; w < 16; w++) m = fmaxf(m, sred[tid * 16 + w]);
        sfin[tid] = m;
    }
    __syncthreads();

    // exp + block sum per g
    #pragma unroll
    for (int g = 0; g < 16; g++) {
        float m = sfin[g];
        e0[g] = __expf(e0[g] - m);
        e1[g] = __expf(e1[g] - m);
        float s = e0[g] + e1[g];
        #pragma unroll
        for (int o = 16; o; o >>= 1) s += __shfl_xor_sync(0xFFFFFFFFu, s, o);
        if (lane == 0) sred[g * 16 + warp] = s;
    }
    __syncthreads();
    if (tid < 16) {
        float s = 0.f;
        #pragma unroll
        for (int w = 0; w < 16; w++) s += sred[tid * 16 + w];
        sinv[tid] = 1.f / s;
    }
    __syncthreads();

    #pragma unroll
    for (int g = 0; g < 16; g++) {
        float inv = sinv[g];
        e0[g] *= inv; e1[g] *= inv;
    }

    #pragma unroll
    for (int gp = 0; gp < 16; gp++) {
        float o0 = 0.f, o1 = 0.f;
        #pragma unroll
        for (int g = 0; g < 16; g++) {
            float w = spost[g * 16 + gp];
            o0 += e0[g] * w; o1 += e1[g] * w;
        }
        bf16 h0, l0, h1, l1;
        split_bf16(o0, h0, l0); split_bf16(o1, h1, l1);
        long long idx = base + (long long)gp * NSEQ * NSEQ + j0;
        *reinterpret_cast<bf162*>(&ah[idx]) = __halves2bfloat162(h0, h1);
        *reinterpret_cast<bf162*>(&al[idx]) = __halves2bfloat162(l0, l1);
    }
}

// ---------------------------------------------------------------------------
static inline int smem_bytes(int BM, int BN, int BK, bool BT, int nwarp) {
    int szA = BM * (BK + 8);
    int szB = BT ? BN * (BK + 8) : BK * (BN + 8);
    int tail = 16 * (BN + 4) * 4;
    int scratch = nwarp * 16 * 20 * 4;
    if (scratch > tail) tail = scratch;
    return (4 * szA + 4 * szB) * 2 + tail;
}

extern "C" void kernel_launch(void* const* d_in, const int* in_sizes, int n_in,
                              void* d_out, int out_size) {
    const float* x        = (const float*)d_in[0];
    const float* Wq       = (const float*)d_in[1];
    const float* Wkv      = (const float*)d_in[2];
    const float* mix_pre  = (const float*)d_in[3];
    const float* mix_post = (const float*)d_in[4];
    const float* Wo       = (const float*)d_in[5];
    const float* bo       = (const float*)d_in[6];
    float* out = (float*)d_out;

    bf16 *xh, *xl, *wqh, *wql, *wkvh, *wkvl, *woh, *wol;
    bf16 *qh, *ql, *kvh, *kvl, *ah, *al, *mh, *ml;
    float* dots;
    cudaGetSymbolAddress((void**)&xh, g_xh);   cudaGetSymbolAddress((void**)&xl, g_xl);
    cudaGetSymbolAddress((void**)&wqh, g_wqh); cudaGetSymbolAddress((void**)&wql, g_wql);
    cudaGetSymbolAddress((void**)&wkvh, g_wkvh); cudaGetSymbolAddress((void**)&wkvl, g_wkvl);
    cudaGetSymbolAddress((void**)&woh, g_woh); cudaGetSymbolAddress((void**)&wol, g_wol);
    cudaGetSymbolAddress((void**)&qh, g_qh);   cudaGetSymbolAddress((void**)&ql, g_ql);
    cudaGetSymbolAddress((void**)&kvh, g_kvh); cudaGetSymbolAddress((void**)&kvl, g_kvl);
    cudaGetSymbolAddress((void**)&ah, g_ah);   cudaGetSymbolAddress((void**)&al, g_al);
    cudaGetSymbolAddress((void**)&mh, g_mh);   cudaGetSymbolAddress((void**)&ml, g_ml);
    cudaGetSymbolAddress((void**)&dots, g_dots);

    // 0) split inputs
    split_kernel<<<(int)(NELEM_X / 4 + 255) / 256, 256>>>(x, xh, xl, (int)(NELEM_X / 4));
    split_kernel<<<(int)(NELEM_WQ / 4 + 255) / 256, 256>>>(Wq, wqh, wql, (int)(NELEM_WQ / 4));
    split_kernel<<<(int)(NELEM_WKV / 4 + 255) / 256, 256>>>(Wkv, wkvh, wkvl, (int)(NELEM_WKV / 4));
    split_kernel<<<(int)(NELEM_WO / 4 + 255) / 256, 256>>>(Wo, woh, wol, (int)(NELEM_WO / 4));

    // GEMM configs
    const int SM_BIG   = smem_bytes(128, 128, 32, false, 8); // proj / out
    const int SM_DOTS  = smem_bytes(128, 128, 32, true,  8);
    const int SM_AV    = smem_bytes(128,  64, 32, false, 4);

    cudaFuncSetAttribute((const void*)gemm_sp<128,128,32,64,32,false,2>,
                         cudaFuncAttributeMaxDynamicSharedMemorySize, SM_BIG);
    cudaFuncSetAttribute((const void*)gemm_sp<128,128,32,64,32,true,0>,
                         cudaFuncAttributeMaxDynamicSharedMemorySize, SM_DOTS);
    cudaFuncSetAttribute((const void*)gemm_sp<128,64,32,64,32,false,2>,
                         cudaFuncAttributeMaxDynamicSharedMemorySize, SM_AV);
    cudaFuncSetAttribute((const void*)gemm_sp<128,128,32,64,32,false,1>,
                         cudaFuncAttributeMaxDynamicSharedMemorySize, SM_BIG);

    // 1) q = SCALE * (x @ Wq)  -> split  [4096,1024]
    gemm_sp<128,128,32,64,32,false,2><<<dim3(8, 32, 1), 256, SM_BIG>>>(
        xh, xl, wqh, wql, nullptr, qh, ql, nullptr,
        DIM, DIM, INNER, INNER, 0, 0, 0, 0, 0, 0, SCALE);

    // 2) kv = x @ Wkv -> split  [4096,2048]
    gemm_sp<128,128,32,64,32,false,2><<<dim3(16, 32, 1), 256, SM_BIG>>>(
        xh, xl, wkvh, wkvl, nullptr, kvh, kvl, nullptr,
        DIM, DIM, 2 * INNER, 2 * INNER, 0, 0, 0, 0, 0, 0, 1.f);

    // 3) dots = q @ k^T (scale already folded into q)   -> f32
    gemm_sp<128,128,32,64,32,true,0><<<dim3(8, 8, BATCH * HEADS), 256, SM_DOTS>>>(
        qh, ql, kvh, kvl, dots, nullptr, nullptr, nullptr,
        DHEAD, INNER, 2 * INNER, NSEQ,
        (long long)NSEQ * INNER, DHEAD,
        (long long)NSEQ * 2 * INNER, DHEAD,
        (long long)HEADS * NSEQ * NSEQ, (long long)NSEQ * NSEQ, 1.f);

    // 4) mix_pre -> softmax -> mix_post -> split attn
    mix_softmax_mix2<<<dim3(NSEQ, BATCH), 512>>>(dots, ah, al, mix_pre, mix_post);

    // 5) mid = attn @ v -> split
    gemm_sp<128,64,32,64,32,false,2><<<dim3(1, 8, BATCH * HEADS), 128, SM_AV>>>(
        ah, al, kvh + INNER, kvl + INNER, nullptr, mh, ml, nullptr,
        NSEQ, NSEQ, 2 * INNER, INNER,
        (long long)HEADS * NSEQ * NSEQ, (long long)NSEQ * NSEQ,
        (long long)NSEQ * 2 * INNER, DHEAD,
        (long long)NSEQ * INNER, DHEAD, 1.f);

    // 6) out = mid @ Wo + bo   -> f32
    gemm_sp<128,128,32,64,32,false,1><<<dim3(8, 32, 1), 256, SM_BIG>>>(
        mh, ml, woh, wol, out, nullptr, nullptr, bo,
        INNER, INNER, DIM, DIM, 0, 0, 0, 0, 0, 0, 1.f);
}

// round 7
// speedup vs baseline: 3.6798x; 1.1972x over previous
#include <cuda_runtime.h>
#include <cuda_bf16.h>
#include <math.h>
#include <cstdint>

#define BATCH 4
#define NSEQ 1024
#define DIM 1024
#define HEADS 16
#define DHEAD 64
#define INNER 1024
#define SCALE 0.125f

typedef __nv_bfloat16 bf16;
typedef __nv_bfloat162 bf162;

// ---------------- scratch (device globals; allocation-free) ----------------
#define NELEM_X   ((long long)BATCH * NSEQ * DIM)
#define NELEM_WQ  ((long long)DIM * INNER)
#define NELEM_WKV ((long long)DIM * 2 * INNER)
#define NELEM_WO  ((long long)INNER * DIM)
#define NELEM_Q   ((long long)BATCH * NSEQ * INNER)
#define NELEM_KV  ((long long)BATCH * NSEQ * 2 * INNER)
#define NELEM_ATT ((long long)BATCH * HEADS * NSEQ * NSEQ)

__device__ bf16 g_xh[NELEM_X],   g_xl[NELEM_X];
__device__ bf16 g_wqh[NELEM_WQ], g_wql[NELEM_WQ];      // Wq  [K=1024, N=1024]
__device__ bf16 g_wkvh[NELEM_WKV], g_wkvl[NELEM_WKV];  // Wkv [K=1024, N=2048]
__device__ bf16 g_woh[NELEM_WO], g_wol[NELEM_WO];      // Wo  [K=1024, N=1024]
__device__ bf16 g_qh[NELEM_Q],   g_ql[NELEM_Q];
__device__ bf16 g_kvh[NELEM_KV], g_kvl[NELEM_KV];
__device__ float g_dots[NELEM_ATT];                    // 256 MB
__device__ bf16 g_ah[NELEM_ATT], g_al[NELEM_ATT];
__device__ bf16 g_mh[NELEM_Q],   g_ml[NELEM_Q];

__device__ __forceinline__ void split_bf16(float x, bf16& h, bf16& l) {
    h = __float2bfloat16(x);
    l = __float2bfloat16(x - __bfloat162float(h));
}
__device__ __forceinline__ uint32_t smem_u32(const void* p) {
    return (uint32_t)__cvta_generic_to_shared(p);
}
__device__ __forceinline__ void cp16(uint32_t s, const void* g) {
    asm volatile("cp.async.cg.shared.global [%0], [%1], 16;" :: "r"(s), "l"(g));
}
__device__ __forceinline__ void cp_commit() { asm volatile("cp.async.commit_group;"); }
template<int N>
__device__ __forceinline__ void cp_wait() { asm volatile("cp.async.wait_group %0;" :: "n"(N)); }

__device__ __forceinline__ void ldsm4(uint32_t* r, uint32_t a) {
    asm volatile("ldmatrix.sync.aligned.m8n8.x4.shared.b16 {%0,%1,%2,%3}, [%4];"
                 : "=r"(r[0]), "=r"(r[1]), "=r"(r[2]), "=r"(r[3]) : "r"(a));
}
__device__ __forceinline__ void ldsm4t(uint32_t* r, uint32_t a) {
    asm volatile("ldmatrix.sync.aligned.m8n8.x4.trans.shared.b16 {%0,%1,%2,%3}, [%4];"
                 : "=r"(r[0]), "=r"(r[1]), "=r"(r[2]), "=r"(r[3]) : "r"(a));
}
__device__ __forceinline__ void mma16816(float* c, const uint32_t* a, const uint32_t* b) {
    asm volatile("mma.sync.aligned.m16n8k16.row.col.f32.bf16.bf16.f32 "
                 "{%0,%1,%2,%3}, {%4,%5,%6,%7}, {%8,%9}, {%0,%1,%2,%3};"
                 : "+f"(c[0]), "+f"(c[1]), "+f"(c[2]), "+f"(c[3])
                 : "r"(a[0]), "r"(a[1]), "r"(a[2]), "r"(a[3]), "r"(b[0]), "r"(b[1]));
}

// ---------------- split: f32 -> bf16 hi/lo ----------------------------------
__global__ void split_kernel(const float* __restrict__ in, bf16* __restrict__ hi,
                             bf16* __restrict__ lo, int n4) {
    int i = blockIdx.x * blockDim.x + threadIdx.x;
    if (i >= n4) return;
    float4 v = reinterpret_cast<const float4*>(in)[i];
    bf16 h0, l0, h1, l1, h2, l2, h3, l3;
    split_bf16(v.x, h0, l0); split_bf16(v.y, h1, l1);
    split_bf16(v.z, h2, l2); split_bf16(v.w, h3, l3);
    reinterpret_cast<bf162*>(hi)[i * 2]     = __halves2bfloat162(h0, h1);
    reinterpret_cast<bf162*>(hi)[i * 2 + 1] = __halves2bfloat162(h2, h3);
    reinterpret_cast<bf162*>(lo)[i * 2]     = __halves2bfloat162(l0, l1);
    reinterpret_cast<bf162*>(lo)[i * 2 + 1] = __halves2bfloat162(l2, l3);
}

// ---------------------------------------------------------------------------
// Raw mma.sync split-bf16 3-term GEMM, 3-stage cp.async pipeline.
//   C[128, BN-tile] = out_scale * A @ op(B) (+bias)
//   A: [M,K] row-major split hi/lo.
//   BTRANS=false: B is [N,K] row-major (dots: k).    ldmatrix
//   BTRANS=true:  B is [K,N] row-major (W / v).      ldmatrix.trans
//   OUT: 0 = f32, 1 = f32 + bias, 2 = split bf16 hi/lo.
// Batched over blockIdx.z (z = zb*16 + zh).
// ---------------------------------------------------------------------------
template<int BN, int NWARP, bool BTRANS, int OUT>
__global__ void __launch_bounds__(NWARP * 32)
mma_gemm(const bf16* __restrict__ Ah, const bf16* __restrict__ Al,
         const bf16* __restrict__ Bh, const bf16* __restrict__ Bl,
         float* __restrict__ Cf, bf16* __restrict__ Ch, bf16* __restrict__ Cl,
         const float* __restrict__ bias,
         int K, int lda, int ldb, int ldc,
         long long sa_b, long long sa_h,
         long long sb_b, long long sb_h,
         long long sc_b, long long sc_h,
         float out_scale)
{
    constexpr int NT = NWARP * 32;
    constexpr int WARPS_N = BN / 32;
    constexpr int LDA_S = 40;                 // 80B row stride: 16B-aligned, odd phase
    constexpr int LDBT = BN + 8;              // trans rows: (BN+8)*2 bytes, odd phase
    constexpr int SA_E = 128 * LDA_S;         // elems per half-stage
    constexpr int SB_E = BTRANS ? 32 * LDBT : BN * LDA_S;
    constexpr int BNP = BN + 4;

    extern __shared__ char smem[];
    const uint32_t aAh = smem_u32(smem);
    const uint32_t aAl = aAh + 3 * SA_E * 2;
    const uint32_t aBh = aAl + 3 * SA_E * 2;
    const uint32_t aBl = aBh + 3 * SB_E * 2;
    float* sE = reinterpret_cast<float*>(smem);

    const int tid = threadIdx.x;
    const int warp = tid >> 5, lane = tid & 31;
    const int wm = (warp / WARPS_N) * 64;
    const int wn = (warp % WARPS_N) * 32;

    const int z = blockIdx.z, zb = z >> 4, zh = z & 15;
    Ah += zb * sa_b + zh * sa_h;  Al += zb * sa_b + zh * sa_h;
    Bh += zb * sb_b + zh * sb_h;  Bl += zb * sb_b + zh * sb_h;
    if (OUT == 2) { Ch += zb * sc_b + zh * sc_h; Cl += zb * sc_b + zh * sc_h; }
    else          { Cf += zb * sc_b + zh * sc_h; }

    const int bm = blockIdx.y * 128, bn = blockIdx.x * BN;

    float acc[4][4][4] = {};

    auto load_stage = [&](int s) {
        const int buf = s % 3;
        const int k0 = s * 32;
        const uint32_t bA = (uint32_t)buf * SA_E * 2;
        const uint32_t bB = (uint32_t)buf * SB_E * 2;
        #pragma unroll
        for (int c = tid; c < 512; c += NT) {          // A: 128 rows x 4 16B chunks
            int r = c >> 2, ck = (c & 3) * 8;
            long long g = (long long)(bm + r) * lda + k0 + ck;
            uint32_t so = bA + (uint32_t)(r * LDA_S + ck) * 2;
            cp16(aAh + so, Ah + g);
            cp16(aAl + so, Al + g);
        }
        if (BTRANS) {
            #pragma unroll
            for (int c = tid; c < 32 * (BN / 8); c += NT) {
                int kr = c / (BN / 8), nc = (c % (BN / 8)) * 8;
                long long g = (long long)(k0 + kr) * ldb + bn + nc;
                uint32_t so = bB + (uint32_t)(kr * LDBT + nc) * 2;
                cp16(aBh + so, Bh + g);
                cp16(aBl + so, Bl + g);
            }
        } else {
            #pragma unroll
            for (int c = tid; c < BN * 4; c += NT) {
                int r = c >> 2, ck = (c & 3) * 8;
                long long g = (long long)(bn + r) * ldb + k0 + ck;
                uint32_t so = bB + (uint32_t)(r * LDA_S + ck) * 2;
                cp16(aBh + so, Bh + g);
                cp16(aBl + so, Bl + g);
            }
        }
        cp_commit();
    };

    const int S = K / 32;
    load_stage(0);
    if (S > 1) load_stage(1);

    for (int s = 0; s < S; s++) {
        if (s + 1 < S) cp_wait<1>(); else cp_wait<0>();
        __syncthreads();
        if (s + 2 < S) load_stage(s + 2);

        const int buf = s % 3;
        const uint32_t bA = (uint32_t)buf * SA_E * 2;
        const uint32_t bB = (uint32_t)buf * SB_E * 2;

        #pragma unroll
        for (int kk = 0; kk < 32; kk += 16) {
            uint32_t a_h[4][4], a_l[4][4];
            #pragma unroll
            for (int mi = 0; mi < 4; mi++) {
                uint32_t ao = bA + (uint32_t)((wm + mi * 16 + (lane & 15)) * LDA_S
                                              + kk + (lane >> 4) * 8) * 2;
                ldsm4(a_h[mi], aAh + ao);
                ldsm4(a_l[mi], aAl + ao);
            }
            uint32_t b_h[4][2], b_l[4][2];
            #pragma unroll
            for (int ni = 0; ni < 2; ni++) {
                uint32_t r4[4];
                if (BTRANS) {
                    uint32_t bo = bB + (uint32_t)((kk + (lane & 15)) * LDBT
                                                  + wn + ni * 16 + (lane >> 4) * 8) * 2;
                    ldsm4t(r4, aBh + bo);
                    b_h[2*ni][0] = r4[0]; b_h[2*ni][1] = r4[1];
                    b_h[2*ni+1][0] = r4[2]; b_h[2*ni+1][1] = r4[3];
                    ldsm4t(r4, aBl + bo);
                    b_l[2*ni][0] = r4[0]; b_l[2*ni][1] = r4[1];
                    b_l[2*ni+1][0] = r4[2]; b_l[2*ni+1][1] = r4[3];
                } else {
                    uint32_t bo = bB + (uint32_t)((wn + ni * 16 + (lane & 15)) * LDA_S
                                                  + kk + (lane >> 4) * 8) * 2;
                    ldsm4(r4, aBh + bo);
                    b_h[2*ni][0] = r4[0]; b_h[2*ni][1] = r4[2];
                    b_h[2*ni+1][0] = r4[1]; b_h[2*ni+1][1] = r4[3];
                    ldsm4(r4, aBl + bo);
                    b_l[2*ni][0] = r4[0]; b_l[2*ni][1] = r4[2];
                    b_l[2*ni+1][0] = r4[1]; b_l[2*ni+1][1] = r4[3];
                }
            }
            #pragma unroll
            for (int mi = 0; mi < 4; mi++)
                #pragma unroll
                for (int ni = 0; ni < 4; ni++) {
                    mma16816(acc[mi][ni], a_h[mi], b_h[ni]);
                    mma16816(acc[mi][ni], a_h[mi], b_l[ni]);
                    mma16816(acc[mi][ni], a_l[mi], b_h[ni]);
                }
        }
    }
    __syncthreads();

    // ---- epilogue: regs -> smem f32 -> coalesced global ----
    #pragma unroll
    for (int mi = 0; mi < 4; mi++) {
        int r0 = wm + mi * 16 + (lane >> 2);
        #pragma unroll
        for (int ni = 0; ni < 4; ni++) {
            int c = wn + ni * 8 + (lane & 3) * 2;
            sE[r0 * BNP + c]           = acc[mi][ni][0];
            sE[r0 * BNP + c + 1]       = acc[mi][ni][1];
            sE[(r0 + 8) * BNP + c]     = acc[mi][ni][2];
            sE[(r0 + 8) * BNP + c + 1] = acc[mi][ni][3];
        }
    }
    __syncthreads();

    for (int i = tid; i < 128 * BN / 2; i += NT) {
        int r = i / (BN / 2), c = (i % (BN / 2)) * 2;
        float v0 = sE[r * BNP + c] * out_scale;
        float v1 = sE[r * BNP + c + 1] * out_scale;
        long long go = (long long)(bm + r) * ldc + bn + c;
        if (OUT == 0) {
            *reinterpret_cast<float2*>(&Cf[go]) = make_float2(v0, v1);
        } else if (OUT == 1) {
            *reinterpret_cast<float2*>(&Cf[go]) =
                make_float2(v0 + bias[bn + c], v1 + bias[bn + c + 1]);
        } else {
            bf16 h0, l0, h1, l1;
            split_bf16(v0, h0, l0); split_bf16(v1, h1, l1);
            *reinterpret_cast<bf162*>(&Ch[go]) = __halves2bfloat162(h0, h1);
            *reinterpret_cast<bf162*>(&Cl[go]) = __halves2bfloat162(l0, l1);
        }
    }
}

// ------------- fused mix_pre -> softmax -> mix_post, register-resident ------
__global__ void mix_softmax_mix2(const float* __restrict__ dots,
                                 bf16* __restrict__ ah, bf16* __restrict__ al,
                                 const float* __restrict__ pre, const float* __restrict__ post) {
    __shared__ float spre[256], spost[256], sred[16 * 16], sfin[16], sinv[16];
    const int tid = threadIdx.x;
    const int i = blockIdx.x, b = blockIdx.y;
    if (tid < 256) { spre[tid] = pre[tid]; spost[tid] = post[tid]; }
    __syncthreads();

    const long long base = (long long)b * HEADS * NSEQ * NSEQ + (long long)i * NSEQ;
    const int j0 = tid * 2;
    const int warp = tid >> 5, lane = tid & 31;

    float in0[16], in1[16];
    #pragma unroll
    for (int h = 0; h < 16; h++) {
        float2 v = *reinterpret_cast<const float2*>(&dots[base + (long long)h * NSEQ * NSEQ + j0]);
        in0[h] = v.x; in1[h] = v.y;
    }

    float e0[16], e1[16];
    #pragma unroll
    for (int g = 0; g < 16; g++) {
        float m0 = 0.f, m1 = 0.f;
        #pragma unroll
        for (int h = 0; h < 16; h++) {
            float w = spre[h * 16 + g];
            m0 += in0[h] * w; m1 += in1[h] * w;
        }
        e0[g] = m0; e1[g] = m1;
    }

    #pragma unroll
    for (int g = 0; g < 16; g++) {
        float m = fmaxf(e0[g], e1[g]);
        #pragma unroll
        for (int o = 16; o; o >>= 1) m = fmaxf(m, __shfl_xor_sync(0xFFFFFFFFu, m, o));
        if (lane == 0) sred[g * 16 + warp] = m;
    }
    __syncthreads();
    if (tid < 16) {
        float m = -INFINITY;
        #pragma unroll
        for (int w = 0; w < 16; w++) m = fmaxf(m, sred[tid * 16 + w]);
        sfin[tid] = m;
    }
    __syncthreads();

    #pragma unroll
    for (int g = 0; g < 16; g++) {
        float m = sfin[g];
        e0[g] = __expf(e0[g] - m);
        e1[g] = __expf(e1[g] - m);
        float s = e0[g] + e1[g];
        #pragma unroll
        for (int o = 16; o; o >>= 1) s += __shfl_xor_sync(0xFFFFFFFFu, s, o);
        if (lane == 0) sred[g * 16 + warp] = s;
    }
    __syncthreads();
    if (tid < 16) {
        float s = 0.f;
        #pragma unroll
        for (int w = 0; w < 16; w++) s += sred[tid * 16 + w];
        sinv[tid] = 1.f / s;
    }
    __syncthreads();

    #pragma unroll
    for (int g = 0; g < 16; g++) {
        float inv = sinv[g];
        e0[g] *= inv; e1[g] *= inv;
    }

    #pragma unroll
    for (int gp = 0; gp < 16; gp++) {
        float o0 = 0.f, o1 = 0.f;
        #pragma unroll
        for (int g = 0; g < 16; g++) {
            float w = spost[g * 16 + gp];
            o0 += e0[g] * w; o1 += e1[g] * w;
        }
        bf16 h0, l0, h1, l1;
        split_bf16(o0, h0, l0); split_bf16(o1, h1, l1);
        long long idx = base + (long long)gp * NSEQ * NSEQ + j0;
        *reinterpret_cast<bf162*>(&ah[idx]) = __halves2bfloat162(h0, h1);
        *reinterpret_cast<bf162*>(&al[idx]) = __halves2bfloat162(l0, l1);
    }
}

// ---------------------------------------------------------------------------
static inline int gemm_smem(int BN, bool BT) {
    int SA = 128 * 40;
    int SB = BT ? 32 * (BN + 8) : BN * 40;
    int pipe = 12 * (SA + SB);          // 3 stages x (hi+lo A + hi+lo B) x 2B
    int epi = 128 * (BN + 4) * 4;
    return pipe > epi ? pipe : epi;
}

extern "C" void kernel_launch(void* const* d_in, const int* in_sizes, int n_in,
                              void* d_out, int out_size) {
    const float* x        = (const float*)d_in[0];
    const float* Wq       = (const float*)d_in[1];
    const float* Wkv      = (const float*)d_in[2];
    const float* mix_pre  = (const float*)d_in[3];
    const float* mix_post = (const float*)d_in[4];
    const float* Wo       = (const float*)d_in[5];
    const float* bo       = (const float*)d_in[6];
    float* out = (float*)d_out;

    bf16 *xh, *xl, *wqh, *wql, *wkvh, *wkvl, *woh, *wol;
    bf16 *qh, *ql, *kvh, *kvl, *ah, *al, *mh, *ml;
    float* dots;
    cudaGetSymbolAddress((void**)&xh, g_xh);     cudaGetSymbolAddress((void**)&xl, g_xl);
    cudaGetSymbolAddress((void**)&wqh, g_wqh);   cudaGetSymbolAddress((void**)&wql, g_wql);
    cudaGetSymbolAddress((void**)&wkvh, g_wkvh); cudaGetSymbolAddress((void**)&wkvl, g_wkvl);
    cudaGetSymbolAddress((void**)&woh, g_woh);   cudaGetSymbolAddress((void**)&wol, g_wol);
    cudaGetSymbolAddress((void**)&qh, g_qh);     cudaGetSymbolAddress((void**)&ql, g_ql);
    cudaGetSymbolAddress((void**)&kvh, g_kvh);   cudaGetSymbolAddress((void**)&kvl, g_kvl);
    cudaGetSymbolAddress((void**)&ah, g_ah);     cudaGetSymbolAddress((void**)&al, g_al);
    cudaGetSymbolAddress((void**)&mh, g_mh);     cudaGetSymbolAddress((void**)&ml, g_ml);
    cudaGetSymbolAddress((void**)&dots, g_dots);

    // 0) split inputs (natural layouts; no transposes needed)
    split_kernel<<<(int)(NELEM_X / 4 + 255) / 256, 256>>>(x, xh, xl, (int)(NELEM_X / 4));
    split_kernel<<<(int)(NELEM_WQ / 4 + 255) / 256, 256>>>(Wq, wqh, wql, (int)(NELEM_WQ / 4));
    split_kernel<<<(int)(NELEM_WKV / 4 + 255) / 256, 256>>>(Wkv, wkvh, wkvl, (int)(NELEM_WKV / 4));
    split_kernel<<<(int)(NELEM_WO / 4 + 255) / 256, 256>>>(Wo, woh, wol, (int)(NELEM_WO / 4));

    const int SM_PROJ = gemm_smem(128, true);   // 113664
    const int SM_DOTS = gemm_smem(128, false);  // 122880
    const int SM_AV   = gemm_smem(64, true);    // 89088

    cudaFuncSetAttribute((const void*)mma_gemm<128,8,true,2>,
                         cudaFuncAttributeMaxDynamicSharedMemorySize, SM_PROJ);
    cudaFuncSetAttribute((const void*)mma_gemm<128,8,false,0>,
                         cudaFuncAttributeMaxDynamicSharedMemorySize, SM_DOTS);
    cudaFuncSetAttribute((const void*)mma_gemm<64,4,true,2>,
                         cudaFuncAttributeMaxDynamicSharedMemorySize, SM_AV);
    cudaFuncSetAttribute((const void*)mma_gemm<128,8,true,1>,
                         cudaFuncAttributeMaxDynamicSharedMemorySize, SM_PROJ);

    // 1) q = SCALE * (x @ Wq) -> split      [4096,1024]
    mma_gemm<128,8,true,2><<<dim3(8, 32, 1), 256, SM_PROJ>>>(
        xh, xl, wqh, wql, nullptr, qh, ql, nullptr,
        DIM, DIM, INNER, INNER, 0, 0, 0, 0, 0, 0, SCALE);

    // 2) kv = x @ Wkv -> split              [4096,2048]
    mma_gemm<128,8,true,2><<<dim3(16, 32, 1), 256, SM_PROJ>>>(
        xh, xl, wkvh, wkvl, nullptr, kvh, kvl, nullptr,
        DIM, DIM, 2 * INNER, 2 * INNER, 0, 0, 0, 0, 0, 0, 1.f);

    // 3) dots = q @ k^T -> f32, batched z=(b,h), K=64
    mma_gemm<128,8,false,0><<<dim3(8, 8, BATCH * HEADS), 256, SM_DOTS>>>(
        qh, ql, kvh, kvl, dots, nullptr, nullptr, nullptr,
        DHEAD, INNER, 2 * INNER, NSEQ,
        (long long)NSEQ * INNER, DHEAD,
        (long long)NSEQ * 2 * INNER, DHEAD,
        (long long)HEADS * NSEQ * NSEQ, (long long)NSEQ * NSEQ, 1.f);

    // 4) mix_pre -> softmax -> mix_post -> split attn
    mix_softmax_mix2<<<dim3(NSEQ, BATCH), 512>>>(dots, ah, al, mix_pre, mix_post);

    // 5) mid = attn @ v -> split, batched z=(b,g), v natural [j, c] layout
    mma_gemm<64,4,true,2><<<dim3(1, 8, BATCH * HEADS), 128, SM_AV>>>(
        ah, al, kvh + INNER, kvl + INNER, nullptr, mh, ml, nullptr,
        NSEQ, NSEQ, 2 * INNER, INNER,
        (long long)HEADS * NSEQ * NSEQ, (long long)NSEQ * NSEQ,
        (long long)NSEQ * 2 * INNER, DHEAD,
        (long long)NSEQ * INNER, DHEAD, 1.f);

    // 6) out = mid @ Wo + bo -> f32          [4096,1024]
    mma_gemm<128,8,true,1><<<dim3(8, 32, 1), 256, SM_PROJ>>>(
        mh, ml, woh, wol, out, nullptr, nullptr, bo,
        INNER, INNER, DIM, DIM, 0, 0, 0, 0, 0, 0, 1.f);
}

// round 8
// speedup vs baseline: 3.9436x; 1.0717x over previous
#include <cuda_runtime.h>
#include <cuda_fp16.h>
#include <math.h>
#include <cstdint>

#define BATCH 4
#define NSEQ 1024
#define DIM 1024
#define HEADS 16
#define DHEAD 64
#define INNER 1024
#define SCALE 0.125f

typedef __half f16;
typedef __half2 f162;

// ---------------- scratch (device globals; allocation-free) ----------------
#define NELEM_X   ((long long)BATCH * NSEQ * DIM)
#define NELEM_WQ  ((long long)DIM * INNER)
#define NELEM_WKV ((long long)DIM * 2 * INNER)
#define NELEM_WO  ((long long)INNER * DIM)
#define NELEM_Q   ((long long)BATCH * NSEQ * INNER)
#define NELEM_KV  ((long long)BATCH * NSEQ * 2 * INNER)
#define NELEM_ATT ((long long)BATCH * HEADS * NSEQ * NSEQ)

__device__ f16 g_xh[NELEM_X],   g_xl[NELEM_X];
__device__ f16 g_wqh[NELEM_WQ], g_wql[NELEM_WQ];
__device__ f16 g_wkvh[NELEM_WKV], g_wkvl[NELEM_WKV];
__device__ f16 g_woh[NELEM_WO], g_wol[NELEM_WO];
__device__ f16 g_qh[NELEM_Q],   g_ql[NELEM_Q];
__device__ f16 g_kvh[NELEM_KV], g_kvl[NELEM_KV];
__device__ float g_dots[NELEM_ATT];     // 256 MB
__device__ f16 g_ah[NELEM_ATT];         // attn hi only (128 MB)
__device__ f16 g_mh[NELEM_Q];           // mid hi only

__device__ __forceinline__ void split_f16(float x, f16& h, f16& l) {
    h = __float2half(x);
    l = __float2half(x - __half2float(h));
}
__device__ __forceinline__ void cp16(uint32_t s, const void* g) {
    asm volatile("cp.async.cg.shared.global [%0], [%1], 16;" :: "r"(s), "l"(g));
}
__device__ __forceinline__ void cp_commit() { asm volatile("cp.async.commit_group;"); }
template<int N>
__device__ __forceinline__ void cp_wait() { asm volatile("cp.async.wait_group %0;" :: "n"(N)); }

__device__ __forceinline__ void ldsm4(uint32_t* r, uint32_t a) {
    asm volatile("ldmatrix.sync.aligned.m8n8.x4.shared.b16 {%0,%1,%2,%3}, [%4];"
                 : "=r"(r[0]), "=r"(r[1]), "=r"(r[2]), "=r"(r[3]) : "r"(a));
}
__device__ __forceinline__ void ldsm4t(uint32_t* r, uint32_t a) {
    asm volatile("ldmatrix.sync.aligned.m8n8.x4.trans.shared.b16 {%0,%1,%2,%3}, [%4];"
                 : "=r"(r[0]), "=r"(r[1]), "=r"(r[2]), "=r"(r[3]) : "r"(a));
}
__device__ __forceinline__ void mma16816(float* c, const uint32_t* a, const uint32_t* b) {
    asm volatile("mma.sync.aligned.m16n8k16.row.col.f32.f16.f16.f32 "
                 "{%0,%1,%2,%3}, {%4,%5,%6,%7}, {%8,%9}, {%0,%1,%2,%3};"
                 : "+f"(c[0]), "+f"(c[1]), "+f"(c[2]), "+f"(c[3])
                 : "r"(a[0]), "r"(a[1]), "r"(a[2]), "r"(a[3]), "r"(b[0]), "r"(b[1]));
}

// ---------------- split: f32 -> f16 hi/lo -----------------------------------
__global__ void split_hl(const float* __restrict__ in, f16* __restrict__ hi,
                         f16* __restrict__ lo, int n4) {
    int i = blockIdx.x * blockDim.x + threadIdx.x;
    if (i >= n4) return;
    float4 v = reinterpret_cast<const float4*>(in)[i];
    f16 h0, l0, h1, l1, h2, l2, h3, l3;
    split_f16(v.x, h0, l0); split_f16(v.y, h1, l1);
    split_f16(v.z, h2, l2); split_f16(v.w, h3, l3);
    reinterpret_cast<f162*>(hi)[i * 2]     = __halves2half2(h0, h1);
    reinterpret_cast<f162*>(hi)[i * 2 + 1] = __halves2half2(h2, h3);
    reinterpret_cast<f162*>(lo)[i * 2]     = __halves2half2(l0, l1);
    reinterpret_cast<f162*>(lo)[i * 2 + 1] = __halves2half2(l2, l3);
}

// ---------------------------------------------------------------------------
// Raw mma.sync fp16 split GEMM, 3-stage cp.async pipeline.
//   C[128, BN-tile] = out_scale * A @ op(B) (+bias)
//   TERMS=3: acc = Ah(Bh+Bl) + Al·Bh  (A hi+lo).  TERMS=2: acc = Ah(Bh+Bl).
//   BTRANS=false: B [N,K] row-major (ldmatrix).  true: B [K,N] (ldmatrix.trans).
//   OUT: 0 f32, 1 f32+bias, 2 split f16 hi/lo, 3 f16 hi only.
// ---------------------------------------------------------------------------
template<int BN, int NWARP, bool BTRANS, int TERMS, int OUT>
__global__ void __launch_bounds__(NWARP * 32, TERMS == 2 ? 2 : 1)
mma_gemm(const f16* __restrict__ Ah, const f16* __restrict__ Al,
         const f16* __restrict__ Bh, const f16* __restrict__ Bl,
         float* __restrict__ Cf, f16* __restrict__ Ch, f16* __restrict__ Cl,
         const float* __restrict__ bias,
         int K, int lda, int ldb, int ldc,
         long long sa_b, long long sa_h,
         long long sb_b, long long sb_h,
         long long sc_b, long long sc_h,
         float out_scale)
{
    constexpr int NT = NWARP * 32;
    constexpr int WARPS_N = BN / 32;
    constexpr int LDA_S = 40;                 // 80B rows: 16B-aligned, odd 16B-phase
    constexpr int LDBT = BN + 8;
    constexpr int SA_E = 128 * LDA_S;
    constexpr int SB_E = BTRANS ? 32 * LDBT : BN * LDA_S;
    constexpr int NAH = (TERMS == 3) ? 2 : 1; // A halves stored
    constexpr int BNP = BN + 4;

    extern __shared__ char smem[];
    const uint32_t aAh = (uint32_t)__cvta_generic_to_shared(smem);
    const uint32_t aAl = aAh + 3 * SA_E * 2;                    // only used TERMS==3
    const uint32_t aBh = aAh + 3 * SA_E * 2 * NAH;
    const uint32_t aBl = aBh + 3 * SB_E * 2;
    float* sE = reinterpret_cast<float*>(smem);

    const int tid = threadIdx.x;
    const int warp = tid >> 5, lane = tid & 31;
    const int wm = (warp / WARPS_N) * 64;
    const int wn = (warp % WARPS_N) * 32;

    const int z = blockIdx.z, zb = z >> 4, zh = z & 15;
    Ah += zb * sa_b + zh * sa_h;
    if (TERMS == 3) Al += zb * sa_b + zh * sa_h;
    Bh += zb * sb_b + zh * sb_h;  Bl += zb * sb_b + zh * sb_h;
    if (OUT >= 2) { Ch += zb * sc_b + zh * sc_h; if (OUT == 2) Cl += zb * sc_b + zh * sc_h; }
    else          { Cf += zb * sc_b + zh * sc_h; }

    const int bm = blockIdx.y * 128, bn = blockIdx.x * BN;

    float acc[4][4][4] = {};

    auto load_stage = [&](int s) {
        const int buf = s % 3;
        const int k0 = s * 32;
        const uint32_t bA = (uint32_t)buf * SA_E * 2;
        const uint32_t bB = (uint32_t)buf * SB_E * 2;
        #pragma unroll
        for (int c = tid; c < 512; c += NT) {
            int r = c >> 2, ck = (c & 3) * 8;
            long long g = (long long)(bm + r) * lda + k0 + ck;
            uint32_t so = bA + (uint32_t)(r * LDA_S + ck) * 2;
            cp16(aAh + so, Ah + g);
            if (TERMS == 3) cp16(aAl + so, Al + g);
        }
        if (BTRANS) {
            #pragma unroll
            for (int c = tid; c < 32 * (BN / 8); c += NT) {
                int kr = c / (BN / 8), nc = (c % (BN / 8)) * 8;
                long long g = (long long)(k0 + kr) * ldb + bn + nc;
                uint32_t so = bB + (uint32_t)(kr * LDBT + nc) * 2;
                cp16(aBh + so, Bh + g);
                cp16(aBl + so, Bl + g);
            }
        } else {
            #pragma unroll
            for (int c = tid; c < BN * 4; c += NT) {
                int r = c >> 2, ck = (c & 3) * 8;
                long long g = (long long)(bn + r) * ldb + k0 + ck;
                uint32_t so = bB + (uint32_t)(r * LDA_S + ck) * 2;
                cp16(aBh + so, Bh + g);
                cp16(aBl + so, Bl + g);
            }
        }
        cp_commit();
    };

    const int S = K / 32;
    load_stage(0);
    if (S > 1) load_stage(1);

    for (int s = 0; s < S; s++) {
        if (s + 1 < S) cp_wait<1>(); else cp_wait<0>();
        __syncthreads();
        if (s + 2 < S) load_stage(s + 2);

        const int buf = s % 3;
        const uint32_t bA = (uint32_t)buf * SA_E * 2;
        const uint32_t bB = (uint32_t)buf * SB_E * 2;

        #pragma unroll
        for (int kk = 0; kk < 32; kk += 16) {
            uint32_t a_h[4][4], a_l[4][4];
            #pragma unroll
            for (int mi = 0; mi < 4; mi++) {
                uint32_t ao = bA + (uint32_t)((wm + mi * 16 + (lane & 15)) * LDA_S
                                              + kk + (lane >> 4) * 8) * 2;
                ldsm4(a_h[mi], aAh + ao);
                if (TERMS == 3) ldsm4(a_l[mi], aAl + ao);
            }
            uint32_t b_h[4][2], b_l[4][2];
            #pragma unroll
            for (int ni = 0; ni < 2; ni++) {
                uint32_t r4[4];
                if (BTRANS) {
                    uint32_t bo = bB + (uint32_t)((kk + (lane & 15)) * LDBT
                                                  + wn + ni * 16 + (lane >> 4) * 8) * 2;
                    ldsm4t(r4, aBh + bo);
                    b_h[2*ni][0] = r4[0]; b_h[2*ni][1] = r4[1];
                    b_h[2*ni+1][0] = r4[2]; b_h[2*ni+1][1] = r4[3];
                    ldsm4t(r4, aBl + bo);
                    b_l[2*ni][0] = r4[0]; b_l[2*ni][1] = r4[1];
                    b_l[2*ni+1][0] = r4[2]; b_l[2*ni+1][1] = r4[3];
                } else {
                    uint32_t bo = bB + (uint32_t)((wn + ni * 16 + (lane & 15)) * LDA_S
                                                  + kk + (lane >> 4) * 8) * 2;
                    ldsm4(r4, aBh + bo);
                    b_h[2*ni][0] = r4[0]; b_h[2*ni][1] = r4[2];
                    b_h[2*ni+1][0] = r4[1]; b_h[2*ni+1][1] = r4[3];
                    ldsm4(r4, aBl + bo);
                    b_l[2*ni][0] = r4[0]; b_l[2*ni][1] = r4[2];
                    b_l[2*ni+1][0] = r4[1]; b_l[2*ni+1][1] = r4[3];
                }
            }
            #pragma unroll
            for (int mi = 0; mi < 4; mi++)
                #pragma unroll
                for (int ni = 0; ni < 4; ni++) {
                    mma16816(acc[mi][ni], a_h[mi], b_h[ni]);
                    mma16816(acc[mi][ni], a_h[mi], b_l[ni]);
                    if (TERMS == 3) mma16816(acc[mi][ni], a_l[mi], b_h[ni]);
                }
        }
    }
    __syncthreads();

    // ---- epilogue: regs -> smem f32 -> coalesced global ----
    #pragma unroll
    for (int mi = 0; mi < 4; mi++) {
        int r0 = wm + mi * 16 + (lane >> 2);
        #pragma unroll
        for (int ni = 0; ni < 4; ni++) {
            int c = wn + ni * 8 + (lane & 3) * 2;
            sE[r0 * BNP + c]           = acc[mi][ni][0];
            sE[r0 * BNP + c + 1]       = acc[mi][ni][1];
            sE[(r0 + 8) * BNP + c]     = acc[mi][ni][2];
            sE[(r0 + 8) * BNP + c + 1] = acc[mi][ni][3];
        }
    }
    __syncthreads();

    for (int i = tid; i < 128 * BN / 2; i += NT) {
        int r = i / (BN / 2), c = (i % (BN / 2)) * 2;
        float v0 = sE[r * BNP + c] * out_scale;
        float v1 = sE[r * BNP + c + 1] * out_scale;
        long long go = (long long)(bm + r) * ldc + bn + c;
        if (OUT == 0) {
            *reinterpret_cast<float2*>(&Cf[go]) = make_float2(v0, v1);
        } else if (OUT == 1) {
            *reinterpret_cast<float2*>(&Cf[go]) =
                make_float2(v0 + bias[bn + c], v1 + bias[bn + c + 1]);
        } else if (OUT == 2) {
            f16 h0, l0, h1, l1;
            split_f16(v0, h0, l0); split_f16(v1, h1, l1);
            *reinterpret_cast<f162*>(&Ch[go]) = __halves2half2(h0, h1);
            *reinterpret_cast<f162*>(&Cl[go]) = __halves2half2(l0, l1);
        } else {
            *reinterpret_cast<f162*>(&Ch[go]) =
                __halves2half2(__float2half(v0), __float2half(v1));
        }
    }
}

// ------------- fused mix_pre -> softmax -> mix_post, register-resident ------
__global__ void mix_softmax_mix2(const float* __restrict__ dots,
                                 f16* __restrict__ ah,
                                 const float* __restrict__ pre, const float* __restrict__ post) {
    __shared__ float spre[256], spost[256], sred[16 * 16], sfin[16], sinv[16];
    const int tid = threadIdx.x;
    const int i = blockIdx.x, b = blockIdx.y;
    if (tid < 256) { spre[tid] = pre[tid]; spost[tid] = post[tid]; }
    __syncthreads();

    const long long base = (long long)b * HEADS * NSEQ * NSEQ + (long long)i * NSEQ;
    const int j0 = tid * 2;
    const int warp = tid >> 5, lane = tid & 31;

    float in0[16], in1[16];
    #pragma unroll
    for (int h = 0; h < 16; h++) {
        float2 v = *reinterpret_cast<const float2*>(&dots[base + (long long)h * NSEQ * NSEQ + j0]);
        in0[h] = v.x; in1[h] = v.y;
    }

    float e0[16], e1[16];
    #pragma unroll
    for (int g = 0; g < 16; g++) {
        float m0 = 0.f, m1 = 0.f;
        #pragma unroll
        for (int h = 0; h < 16; h++) {
            float w = spre[h * 16 + g];
            m0 += in0[h] * w; m1 += in1[h] * w;
        }
        e0[g] = m0; e1[g] = m1;
    }

    #pragma unroll
    for (int g = 0; g < 16; g++) {
        float m = fmaxf(e0[g], e1[g]);
        #pragma unroll
        for (int o = 16; o; o >>= 1) m = fmaxf(m, __shfl_xor_sync(0xFFFFFFFFu, m, o));
        if (lane == 0) sred[g * 16 + warp] = m;
    }
    __syncthreads();
    if (tid < 16) {
        float m = -INFINITY;
        #pragma unroll
        for (int w = 0; w < 16; w++) m = fmaxf(m, sred[tid * 16 + w]);
        sfin[tid] = m;
    }
    __syncthreads();

    #pragma unroll
    for (int g = 0; g < 16; g++) {
        float m = sfin[g];
        e0[g] = __expf(e0[g] - m);
        e1[g] = __expf(e1[g] - m);
        float s = e0[g] + e1[g];
        #pragma unroll
        for (int o = 16; o; o >>= 1) s += __shfl_xor_sync(0xFFFFFFFFu, s, o);
        if (lane == 0) sred[g * 16 + warp] = s;
    }
    __syncthreads();
    if (tid < 16) {
        float s = 0.f;
        #pragma unroll
        for (int w = 0; w < 16; w++) s += sred[tid * 16 + w];
        sinv[tid] = 1.f / s;
    }
    __syncthreads();

    #pragma unroll
    for (int g = 0; g < 16; g++) {
        float inv = sinv[g];
        e0[g] *= inv; e1[g] *= inv;
    }

    #pragma unroll
    for (int gp = 0; gp < 16; gp++) {
        float o0 = 0.f, o1 = 0.f;
        #pragma unroll
        for (int g = 0; g < 16; g++) {
            float w = spost[g * 16 + gp];
            o0 += e0[g] * w; o1 += e1[g] * w;
        }
        long long idx = base + (long long)gp * NSEQ * NSEQ + j0;
        *reinterpret_cast<f162*>(&ah[idx]) =
            __halves2half2(__float2half(o0), __float2half(o1));
    }
}

// ---------------------------------------------------------------------------
static inline int gemm_smem(int BN, bool BT, int terms) {
    int SA = 128 * 40 * (terms == 3 ? 2 : 1);
    int SB = 2 * (BT ? 32 * (BN + 8) : BN * 40);
    int pipe = 6 * (SA + SB);           // 3 stages x 2B
    int epi = 128 * (BN + 4) * 4;
    return pipe > epi ? pipe : epi;
}

extern "C" void kernel_launch(void* const* d_in, const int* in_sizes, int n_in,
                              void* d_out, int out_size) {
    const float* x        = (const float*)d_in[0];
    const float* Wq       = (const float*)d_in[1];
    const float* Wkv      = (const float*)d_in[2];
    const float* mix_pre  = (const float*)d_in[3];
    const float* mix_post = (const float*)d_in[4];
    const float* Wo       = (const float*)d_in[5];
    const float* bo       = (const float*)d_in[6];
    float* out = (float*)d_out;

    f16 *xh, *xl, *wqh, *wql, *wkvh, *wkvl, *woh, *wol;
    f16 *qh, *ql, *kvh, *kvl, *ah, *mh;
    float* dots;
    cudaGetSymbolAddress((void**)&xh, g_xh);     cudaGetSymbolAddress((void**)&xl, g_xl);
    cudaGetSymbolAddress((void**)&wqh, g_wqh);   cudaGetSymbolAddress((void**)&wql, g_wql);
    cudaGetSymbolAddress((void**)&wkvh, g_wkvh); cudaGetSymbolAddress((void**)&wkvl, g_wkvl);
    cudaGetSymbolAddress((void**)&woh, g_woh);   cudaGetSymbolAddress((void**)&wol, g_wol);
    cudaGetSymbolAddress((void**)&qh, g_qh);     cudaGetSymbolAddress((void**)&ql, g_ql);
    cudaGetSymbolAddress((void**)&kvh, g_kvh);   cudaGetSymbolAddress((void**)&kvl, g_kvl);
    cudaGetSymbolAddress((void**)&ah, g_ah);
    cudaGetSymbolAddress((void**)&mh, g_mh);
    cudaGetSymbolAddress((void**)&dots, g_dots);

    // 0) split inputs
    split_hl<<<(int)(NELEM_X / 4 + 255) / 256, 256>>>(x, xh, xl, (int)(NELEM_X / 4));
    split_hl<<<(int)(NELEM_WQ / 4 + 255) / 256, 256>>>(Wq, wqh, wql, (int)(NELEM_WQ / 4));
    split_hl<<<(int)(NELEM_WKV / 4 + 255) / 256, 256>>>(Wkv, wkvh, wkvl, (int)(NELEM_WKV / 4));
    split_hl<<<(int)(NELEM_WO / 4 + 255) / 256, 256>>>(Wo, woh, wol, (int)(NELEM_WO / 4));

    const int SM_PROJ = gemm_smem(128, true, 3);   // 113664
    const int SM_DOTS = gemm_smem(128, false, 3);  // 122880
    const int SM_AV   = gemm_smem(64, true, 2);    // 58368
    const int SM_OUT  = gemm_smem(128, true, 2);   // 82944

    cudaFuncSetAttribute((const void*)mma_gemm<128,8,true,3,2>,
                         cudaFuncAttributeMaxDynamicSharedMemorySize, SM_PROJ);
    cudaFuncSetAttribute((const void*)mma_gemm<128,8,false,3,0>,
                         cudaFuncAttributeMaxDynamicSharedMemorySize, SM_DOTS);
    cudaFuncSetAttribute((const void*)mma_gemm<64,4,true,2,3>,
                         cudaFuncAttributeMaxDynamicSharedMemorySize, SM_AV);
    cudaFuncSetAttribute((const void*)mma_gemm<128,8,true,2,1>,
                         cudaFuncAttributeMaxDynamicSharedMemorySize, SM_OUT);

    // 1) q = SCALE * (x @ Wq) -> split hi/lo   [4096,1024]  (3-term)
    mma_gemm<128,8,true,3,2><<<dim3(8, 32, 1), 256, SM_PROJ>>>(
        xh, xl, wqh, wql, nullptr, qh, ql, nullptr,
        DIM, DIM, INNER, INNER, 0, 0, 0, 0, 0, 0, SCALE);

    // 2) kv = x @ Wkv -> split hi/lo           [4096,2048]  (3-term)
    mma_gemm<128,8,true,3,2><<<dim3(16, 32, 1), 256, SM_PROJ>>>(
        xh, xl, wkvh, wkvl, nullptr, kvh, kvl, nullptr,
        DIM, DIM, 2 * INNER, 2 * INNER, 0, 0, 0, 0, 0, 0, 1.f);

    // 3) dots = q @ k^T -> f32, batched z=(b,h), K=64  (3-term)
    mma_gemm<128,8,false,3,0><<<dim3(8, 8, BATCH * HEADS), 256, SM_DOTS>>>(
        qh, ql, kvh, kvl, dots, nullptr, nullptr, nullptr,
        DHEAD, INNER, 2 * INNER, NSEQ,
        (long long)NSEQ * INNER, DHEAD,
        (long long)NSEQ * 2 * INNER, DHEAD,
        (long long)HEADS * NSEQ * NSEQ, (long long)NSEQ * NSEQ, 1.f);

    // 4) mix_pre -> softmax -> mix_post -> attn hi only (fp16)
    mix_softmax_mix2<<<dim3(NSEQ, BATCH), 512>>>(dots, ah, mix_pre, mix_post);

    // 5) mid = attn @ v -> hi only, batched z=(b,g)  (2-term)
    mma_gemm<64,4,true,2,3><<<dim3(1, 8, BATCH * HEADS), 128, SM_AV>>>(
        ah, nullptr, kvh + INNER, kvl + INNER, nullptr, mh, nullptr, nullptr,
        NSEQ, NSEQ, 2 * INNER, INNER,
        (long long)HEADS * NSEQ * NSEQ, (long long)NSEQ * NSEQ,
        (long long)NSEQ * 2 * INNER, DHEAD,
        (long long)NSEQ * INNER, DHEAD, 1.f);

    // 6) out = mid @ Wo + bo -> f32            [4096,1024]  (2-term)
    mma_gemm<128,8,true,2,1><<<dim3(8, 32, 1), 256, SM_OUT>>>(
        mh, nullptr, woh, wol, out, nullptr, nullptr, bo,
        INNER, INNER, DIM, DIM, 0, 0, 0, 0, 0, 0, 1.f);
}

// round 9
// speedup vs baseline: 4.3260x; 1.0969x over previous
#include <cuda_runtime.h>
#include <cuda_fp16.h>
#include <math.h>
#include <cstdint>

#define BATCH 4
#define NSEQ 1024
#define DIM 1024
#define HEADS 16
#define DHEAD 64
#define INNER 1024
#define SCALE 0.125f

typedef __half f16;
typedef __half2 f162;

// ---------------- scratch (device globals; allocation-free) ----------------
#define NELEM_X   ((long long)BATCH * NSEQ * DIM)
#define NELEM_WQ  ((long long)DIM * INNER)
#define NELEM_WKV ((long long)DIM * 2 * INNER)
#define NELEM_WO  ((long long)INNER * DIM)
#define NELEM_Q   ((long long)BATCH * NSEQ * INNER)
#define NELEM_KV  ((long long)BATCH * NSEQ * 2 * INNER)
#define NELEM_ATT ((long long)BATCH * HEADS * NSEQ * NSEQ)

__device__ f16 g_xh[NELEM_X],   g_xl[NELEM_X];
__device__ f16 g_wqh[NELEM_WQ], g_wql[NELEM_WQ];
__device__ f16 g_wkvh[NELEM_WKV], g_wkvl[NELEM_WKV];
__device__ f16 g_woh[NELEM_WO], g_wol[NELEM_WO];
__device__ f16 g_qh[NELEM_Q],   g_ql[NELEM_Q];
__device__ f16 g_kvh[NELEM_KV], g_kvl[NELEM_KV];
__device__ float g_dots[NELEM_ATT];     // 256 MB
__device__ f16 g_ah[NELEM_ATT];         // attn hi only
__device__ f16 g_mh[NELEM_Q];           // mid hi only

__device__ __forceinline__ void split_f16(float x, f16& h, f16& l) {
    h = __float2half(x);
    l = __float2half(x - __half2float(h));
}
__device__ __forceinline__ void cp16(uint32_t s, const void* g) {
    asm volatile("cp.async.cg.shared.global [%0], [%1], 16;" :: "r"(s), "l"(g));
}
__device__ __forceinline__ void cp_commit() { asm volatile("cp.async.commit_group;"); }
template<int N>
__device__ __forceinline__ void cp_wait() { asm volatile("cp.async.wait_group %0;" :: "n"(N)); }

__device__ __forceinline__ void ldsm4(uint32_t* r, uint32_t a) {
    asm volatile("ldmatrix.sync.aligned.m8n8.x4.shared.b16 {%0,%1,%2,%3}, [%4];"
                 : "=r"(r[0]), "=r"(r[1]), "=r"(r[2]), "=r"(r[3]) : "r"(a));
}
__device__ __forceinline__ void ldsm4t(uint32_t* r, uint32_t a) {
    asm volatile("ldmatrix.sync.aligned.m8n8.x4.trans.shared.b16 {%0,%1,%2,%3}, [%4];"
                 : "=r"(r[0]), "=r"(r[1]), "=r"(r[2]), "=r"(r[3]) : "r"(a));
}
__device__ __forceinline__ void mma16816(float* c, const uint32_t* a, const uint32_t* b) {
    asm volatile("mma.sync.aligned.m16n8k16.row.col.f32.f16.f16.f32 "
                 "{%0,%1,%2,%3}, {%4,%5,%6,%7}, {%8,%9}, {%0,%1,%2,%3};"
                 : "+f"(c[0]), "+f"(c[1]), "+f"(c[2]), "+f"(c[3])
                 : "r"(a[0]), "r"(a[1]), "r"(a[2]), "r"(a[3]), "r"(b[0]), "r"(b[1]));
}

// ---------------- split: f32 -> f16 hi/lo -----------------------------------
__global__ void split_hl(const float* __restrict__ in, f16* __restrict__ hi,
                         f16* __restrict__ lo, int n4) {
    int i = blockIdx.x * blockDim.x + threadIdx.x;
    if (i >= n4) return;
    float4 v = reinterpret_cast<const float4*>(in)[i];
    f16 h0, l0, h1, l1, h2, l2, h3, l3;
    split_f16(v.x, h0, l0); split_f16(v.y, h1, l1);
    split_f16(v.z, h2, l2); split_f16(v.w, h3, l3);
    reinterpret_cast<f162*>(hi)[i * 2]     = __halves2half2(h0, h1);
    reinterpret_cast<f162*>(hi)[i * 2 + 1] = __halves2half2(h2, h3);
    reinterpret_cast<f162*>(lo)[i * 2]     = __halves2half2(l0, l1);
    reinterpret_cast<f162*>(lo)[i * 2 + 1] = __halves2half2(l2, l3);
}

// ---------------------------------------------------------------------------
// Raw mma.sync fp16 split GEMM, 2-buffer cp.async pipeline (prefetch-before-
// compute), multi-CTA/SM residency via OCC.
//   TERMS=3: acc = Ah(Bh+Bl) + Al·Bh.   TERMS=2: acc = Ah(Bh+Bl).
//   BTRANS=false: B [N,K] row-major (ldmatrix).  true: B [K,N] (ldmatrix.trans).
//   OUT: 0 f32, 1 f32+bias, 2 split f16 hi/lo, 3 f16 hi only.
// ---------------------------------------------------------------------------
template<int BN, int NWARP, bool BTRANS, int TERMS, int OUT, int OCC>
__global__ void __launch_bounds__(NWARP * 32, OCC)
mma_gemm(const f16* __restrict__ Ah, const f16* __restrict__ Al,
         const f16* __restrict__ Bh, const f16* __restrict__ Bl,
         float* __restrict__ Cf, f16* __restrict__ Ch, f16* __restrict__ Cl,
         const float* __restrict__ bias,
         int K, int lda, int ldb, int ldc,
         long long sa_b, long long sa_h,
         long long sb_b, long long sb_h,
         long long sc_b, long long sc_h,
         float out_scale)
{
    constexpr int NT = NWARP * 32;
    constexpr int WARPS_N = BN / 32;
    constexpr int LDA_S = 40;                 // 80B rows: 16B-aligned, odd 16B-phase
    constexpr int LDBT = BN + 8;
    constexpr int SA_E = 128 * LDA_S;
    constexpr int SB_E = BTRANS ? 32 * LDBT : BN * LDA_S;
    constexpr int NAH = (TERMS == 3) ? 2 : 1;
    constexpr int BNP = BN + 4;

    extern __shared__ char smem[];
    const uint32_t aAh = (uint32_t)__cvta_generic_to_shared(smem);
    const uint32_t aAl = aAh + 2 * SA_E * 2;                 // only if TERMS==3
    const uint32_t aBh = aAh + 2 * SA_E * 2 * NAH;
    const uint32_t aBl = aBh + 2 * SB_E * 2;
    float* sE = reinterpret_cast<float*>(smem);

    const int tid = threadIdx.x;
    const int warp = tid >> 5, lane = tid & 31;
    const int wm = (warp / WARPS_N) * 64;
    const int wn = (warp % WARPS_N) * 32;

    const int z = blockIdx.z, zb = z >> 4, zh = z & 15;
    Ah += zb * sa_b + zh * sa_h;
    if (TERMS == 3) Al += zb * sa_b + zh * sa_h;
    Bh += zb * sb_b + zh * sb_h;  Bl += zb * sb_b + zh * sb_h;
    if (OUT >= 2) { Ch += zb * sc_b + zh * sc_h; if (OUT == 2) Cl += zb * sc_b + zh * sc_h; }
    else          { Cf += zb * sc_b + zh * sc_h; }

    const int bm = blockIdx.y * 128, bn = blockIdx.x * BN;

    float acc[4][4][4] = {};

    auto load_stage = [&](int s) {
        const int buf = s & 1;
        const int k0 = s * 32;
        const uint32_t bA = (uint32_t)buf * SA_E * 2;
        const uint32_t bB = (uint32_t)buf * SB_E * 2;
        #pragma unroll
        for (int c = tid; c < 512; c += NT) {
            int r = c >> 2, ck = (c & 3) * 8;
            long long g = (long long)(bm + r) * lda + k0 + ck;
            uint32_t so = bA + (uint32_t)(r * LDA_S + ck) * 2;
            cp16(aAh + so, Ah + g);
            if (TERMS == 3) cp16(aAl + so, Al + g);
        }
        if (BTRANS) {
            #pragma unroll
            for (int c = tid; c < 32 * (BN / 8); c += NT) {
                int kr = c / (BN / 8), nc = (c % (BN / 8)) * 8;
                long long g = (long long)(k0 + kr) * ldb + bn + nc;
                uint32_t so = bB + (uint32_t)(kr * LDBT + nc) * 2;
                cp16(aBh + so, Bh + g);
                cp16(aBl + so, Bl + g);
            }
        } else {
            #pragma unroll
            for (int c = tid; c < BN * 4; c += NT) {
                int r = c >> 2, ck = (c & 3) * 8;
                long long g = (long long)(bn + r) * ldb + k0 + ck;
                uint32_t so = bB + (uint32_t)(r * LDA_S + ck) * 2;
                cp16(aBh + so, Bh + g);
                cp16(aBl + so, Bl + g);
            }
        }
        cp_commit();
    };

    const int S = K / 32;
    load_stage(0);

    for (int s = 0; s < S; s++) {
        cp_wait<0>();
        __syncthreads();
        if (s + 1 < S) load_stage(s + 1);   // prefetch overlaps compute below

        const int buf = s & 1;
        const uint32_t bA = (uint32_t)buf * SA_E * 2;
        const uint32_t bB = (uint32_t)buf * SB_E * 2;

        #pragma unroll
        for (int kk = 0; kk < 32; kk += 16) {
            uint32_t a_h[4][4], a_l[4][4];
            #pragma unroll
            for (int mi = 0; mi < 4; mi++) {
                uint32_t ao = bA + (uint32_t)((wm + mi * 16 + (lane & 15)) * LDA_S
                                              + kk + (lane >> 4) * 8) * 2;
                ldsm4(a_h[mi], aAh + ao);
                if (TERMS == 3) ldsm4(a_l[mi], aAl + ao);
            }
            uint32_t b_h[4][2], b_l[4][2];
            #pragma unroll
            for (int ni = 0; ni < 2; ni++) {
                uint32_t r4[4];
                if (BTRANS) {
                    uint32_t bo = bB + (uint32_t)((kk + (lane & 15)) * LDBT
                                                  + wn + ni * 16 + (lane >> 4) * 8) * 2;
                    ldsm4t(r4, aBh + bo);
                    b_h[2*ni][0] = r4[0]; b_h[2*ni][1] = r4[1];
                    b_h[2*ni+1][0] = r4[2]; b_h[2*ni+1][1] = r4[3];
                    ldsm4t(r4, aBl + bo);
                    b_l[2*ni][0] = r4[0]; b_l[2*ni][1] = r4[1];
                    b_l[2*ni+1][0] = r4[2]; b_l[2*ni+1][1] = r4[3];
                } else {
                    uint32_t bo = bB + (uint32_t)((wn + ni * 16 + (lane & 15)) * LDA_S
                                                  + kk + (lane >> 4) * 8) * 2;
                    ldsm4(r4, aBh + bo);
                    b_h[2*ni][0] = r4[0]; b_h[2*ni][1] = r4[2];
                    b_h[2*ni+1][0] = r4[1]; b_h[2*ni+1][1] = r4[3];
                    ldsm4(r4, aBl + bo);
                    b_l[2*ni][0] = r4[0]; b_l[2*ni][1] = r4[2];
                    b_l[2*ni+1][0] = r4[1]; b_l[2*ni+1][1] = r4[3];
                }
            }
            #pragma unroll
            for (int mi = 0; mi < 4; mi++)
                #pragma unroll
                for (int ni = 0; ni < 4; ni++) {
                    mma16816(acc[mi][ni], a_h[mi], b_h[ni]);
                    mma16816(acc[mi][ni], a_h[mi], b_l[ni]);
                    if (TERMS == 3) mma16816(acc[mi][ni], a_l[mi], b_h[ni]);
                }
        }
        __syncthreads();
    }

    // ---- epilogue: regs -> smem f32 -> wide coalesced global ----
    #pragma unroll
    for (int mi = 0; mi < 4; mi++) {
        int r0 = wm + mi * 16 + (lane >> 2);
        #pragma unroll
        for (int ni = 0; ni < 4; ni++) {
            int c = wn + ni * 8 + (lane & 3) * 2;
            sE[r0 * BNP + c]           = acc[mi][ni][0];
            sE[r0 * BNP + c + 1]       = acc[mi][ni][1];
            sE[(r0 + 8) * BNP + c]     = acc[mi][ni][2];
            sE[(r0 + 8) * BNP + c + 1] = acc[mi][ni][3];
        }
    }
    __syncthreads();

    for (int i = tid; i < 128 * BN / 4; i += NT) {
        int r = i / (BN / 4), c = (i % (BN / 4)) * 4;
        float v0 = sE[r * BNP + c]     * out_scale;
        float v1 = sE[r * BNP + c + 1] * out_scale;
        float v2 = sE[r * BNP + c + 2] * out_scale;
        float v3 = sE[r * BNP + c + 3] * out_scale;
        long long go = (long long)(bm + r) * ldc + bn + c;
        if (OUT == 0) {
            *reinterpret_cast<float4*>(&Cf[go]) = make_float4(v0, v1, v2, v3);
        } else if (OUT == 1) {
            *reinterpret_cast<float4*>(&Cf[go]) =
                make_float4(v0 + bias[bn + c], v1 + bias[bn + c + 1],
                            v2 + bias[bn + c + 2], v3 + bias[bn + c + 3]);
        } else if (OUT == 2) {
            f16 h0, l0, h1, l1, h2, l2, h3, l3;
            split_f16(v0, h0, l0); split_f16(v1, h1, l1);
            split_f16(v2, h2, l2); split_f16(v3, h3, l3);
            f162 hh[2] = {__halves2half2(h0, h1), __halves2half2(h2, h3)};
            f162 ll[2] = {__halves2half2(l0, l1), __halves2half2(l2, l3)};
            *reinterpret_cast<float2*>(&Ch[go]) = *reinterpret_cast<float2*>(hh);
            *reinterpret_cast<float2*>(&Cl[go]) = *reinterpret_cast<float2*>(ll);
        } else {
            f162 hh[2] = {__halves2half2(__float2half(v0), __float2half(v1)),
                          __halves2half2(__float2half(v2), __float2half(v3))};
            *reinterpret_cast<float2*>(&Ch[go]) = *reinterpret_cast<float2*>(hh);
        }
    }
}

// ------------- fused mix_pre -> softmax -> mix_post, register-resident ------
__global__ void mix_softmax_mix2(const float* __restrict__ dots,
                                 f16* __restrict__ ah,
                                 const float* __restrict__ pre, const float* __restrict__ post) {
    __shared__ float spre[256], spost[256], sred[16 * 16], sfin[16], sinv[16];
    const int tid = threadIdx.x;
    const int i = blockIdx.x, b = blockIdx.y;
    if (tid < 256) { spre[tid] = pre[tid]; spost[tid] = post[tid]; }
    __syncthreads();

    const long long base = (long long)b * HEADS * NSEQ * NSEQ + (long long)i * NSEQ;
    const int j0 = tid * 2;
    const int warp = tid >> 5, lane = tid & 31;

    float in0[16], in1[16];
    #pragma unroll
    for (int h = 0; h < 16; h++) {
        float2 v = *reinterpret_cast<const float2*>(&dots[base + (long long)h * NSEQ * NSEQ + j0]);
        in0[h] = v.x; in1[h] = v.y;
    }

    float e0[16], e1[16];
    #pragma unroll
    for (int g = 0; g < 16; g++) {
        float m0 = 0.f, m1 = 0.f;
        #pragma unroll
        for (int h = 0; h < 16; h++) {
            float w = spre[h * 16 + g];
            m0 += in0[h] * w; m1 += in1[h] * w;
        }
        e0[g] = m0; e1[g] = m1;
    }

    #pragma unroll
    for (int g = 0; g < 16; g++) {
        float m = fmaxf(e0[g], e1[g]);
        #pragma unroll
        for (int o = 16; o; o >>= 1) m = fmaxf(m, __shfl_xor_sync(0xFFFFFFFFu, m, o));
        if (lane == 0) sred[g * 16 + warp] = m;
    }
    __syncthreads();
    if (tid < 16) {
        float m = -INFINITY;
        #pragma unroll
        for (int w = 0; w < 16; w++) m = fmaxf(m, sred[tid * 16 + w]);
        sfin[tid] = m;
    }
    __syncthreads();

    #pragma unroll
    for (int g = 0; g < 16; g++) {
        float m = sfin[g];
        e0[g] = __expf(e0[g] - m);
        e1[g] = __expf(e1[g] - m);
        float s = e0[g] + e1[g];
        #pragma unroll
        for (int o = 16; o; o >>= 1) s += __shfl_xor_sync(0xFFFFFFFFu, s, o);
        if (lane == 0) sred[g * 16 + warp] = s;
    }
    __syncthreads();
    if (tid < 16) {
        float s = 0.f;
        #pragma unroll
        for (int w = 0; w < 16; w++) s += sred[tid * 16 + w];
        sinv[tid] = 1.f / s;
    }
    __syncthreads();

    #pragma unroll
    for (int g = 0; g < 16; g++) {
        float inv = sinv[g];
        e0[g] *= inv; e1[g] *= inv;
    }

    #pragma unroll
    for (int gp = 0; gp < 16; gp++) {
        float o0 = 0.f, o1 = 0.f;
        #pragma unroll
        for (int g = 0; g < 16; g++) {
            float w = spost[g * 16 + gp];
            o0 += e0[g] * w; o1 += e1[g] * w;
        }
        long long idx = base + (long long)gp * NSEQ * NSEQ + j0;
        *reinterpret_cast<f162*>(&ah[idx]) =
            __halves2half2(__float2half(o0), __float2half(o1));
    }
}

// ---------------------------------------------------------------------------
static inline int gemm_smem(int BN, bool BT, int terms) {
    int SA = 128 * 40 * (terms == 3 ? 2 : 1);
    int SB = 2 * (BT ? 32 * (BN + 8) : BN * 40);
    int pipe = 4 * (SA + SB);           // 2 stages x 2B
    int epi = 128 * (BN + 4) * 4;
    return pipe > epi ? pipe : epi;
}

extern "C" void kernel_launch(void* const* d_in, const int* in_sizes, int n_in,
                              void* d_out, int out_size) {
    const float* x        = (const float*)d_in[0];
    const float* Wq       = (const float*)d_in[1];
    const float* Wkv      = (const float*)d_in[2];
    const float* mix_pre  = (const float*)d_in[3];
    const float* mix_post = (const float*)d_in[4];
    const float* Wo       = (const float*)d_in[5];
    const float* bo       = (const float*)d_in[6];
    float* out = (float*)d_out;

    f16 *xh, *xl, *wqh, *wql, *wkvh, *wkvl, *woh, *wol;
    f16 *qh, *ql, *kvh, *kvl, *ah, *mh;
    float* dots;
    cudaGetSymbolAddress((void**)&xh, g_xh);     cudaGetSymbolAddress((void**)&xl, g_xl);
    cudaGetSymbolAddress((void**)&wqh, g_wqh);   cudaGetSymbolAddress((void**)&wql, g_wql);
    cudaGetSymbolAddress((void**)&wkvh, g_wkvh); cudaGetSymbolAddress((void**)&wkvl, g_wkvl);
    cudaGetSymbolAddress((void**)&woh, g_woh);   cudaGetSymbolAddress((void**)&wol, g_wol);
    cudaGetSymbolAddress((void**)&qh, g_qh);     cudaGetSymbolAddress((void**)&ql, g_ql);
    cudaGetSymbolAddress((void**)&kvh, g_kvh);   cudaGetSymbolAddress((void**)&kvl, g_kvl);
    cudaGetSymbolAddress((void**)&ah, g_ah);
    cudaGetSymbolAddress((void**)&mh, g_mh);
    cudaGetSymbolAddress((void**)&dots, g_dots);

    // 0) split inputs
    split_hl<<<(int)(NELEM_X / 4 + 255) / 256, 256>>>(x, xh, xl, (int)(NELEM_X / 4));
    split_hl<<<(int)(NELEM_WQ / 4 + 255) / 256, 256>>>(Wq, wqh, wql, (int)(NELEM_WQ / 4));
    split_hl<<<(int)(NELEM_WKV / 4 + 255) / 256, 256>>>(Wkv, wkvh, wkvl, (int)(NELEM_WKV / 4));
    split_hl<<<(int)(NELEM_WO / 4 + 255) / 256, 256>>>(Wo, woh, wol, (int)(NELEM_WO / 4));

    const int SM_PROJ = gemm_smem(128, true, 3);   // 75776
    const int SM_DOTS = gemm_smem(128, false, 3);  // 81920
    const int SM_AV   = gemm_smem(64, true, 2);    // 38912
    const int SM_OUT  = gemm_smem(128, true, 2);   // 67584 (epi-bound)

    cudaFuncSetAttribute((const void*)mma_gemm<128,8,true,3,2,2>,
                         cudaFuncAttributeMaxDynamicSharedMemorySize, SM_PROJ);
    cudaFuncSetAttribute((const void*)mma_gemm<128,8,false,3,0,2>,
                         cudaFuncAttributeMaxDynamicSharedMemorySize, SM_DOTS);
    cudaFuncSetAttribute((const void*)mma_gemm<64,4,true,2,3,3>,
                         cudaFuncAttributeMaxDynamicSharedMemorySize, SM_AV);
    cudaFuncSetAttribute((const void*)mma_gemm<128,8,true,2,1,2>,
                         cudaFuncAttributeMaxDynamicSharedMemorySize, SM_OUT);

    // 1) q = SCALE * (x @ Wq) -> split hi/lo   (3-term)
    mma_gemm<128,8,true,3,2,2><<<dim3(8, 32, 1), 256, SM_PROJ>>>(
        xh, xl, wqh, wql, nullptr, qh, ql, nullptr,
        DIM, DIM, INNER, INNER, 0, 0, 0, 0, 0, 0, SCALE);

    // 2) kv = x @ Wkv -> split hi/lo           (3-term)
    mma_gemm<128,8,true,3,2,2><<<dim3(16, 32, 1), 256, SM_PROJ>>>(
        xh, xl, wkvh, wkvl, nullptr, kvh, kvl, nullptr,
        DIM, DIM, 2 * INNER, 2 * INNER, 0, 0, 0, 0, 0, 0, 1.f);

    // 3) dots = q @ k^T -> f32, batched z=(b,h), K=64  (3-term)
    mma_gemm<128,8,false,3,0,2><<<dim3(8, 8, BATCH * HEADS), 256, SM_DOTS>>>(
        qh, ql, kvh, kvl, dots, nullptr, nullptr, nullptr,
        DHEAD, INNER, 2 * INNER, NSEQ,
        (long long)NSEQ * INNER, DHEAD,
        (long long)NSEQ * 2 * INNER, DHEAD,
        (long long)HEADS * NSEQ * NSEQ, (long long)NSEQ * NSEQ, 1.f);

    // 4) mix_pre -> softmax -> mix_post -> attn hi (fp16)
    mix_softmax_mix2<<<dim3(NSEQ, BATCH), 512>>>(dots, ah, mix_pre, mix_post);

    // 5) mid = attn @ v -> hi only, batched z=(b,g)  (2-term)
    mma_gemm<64,4,true,2,3,3><<<dim3(1, 8, BATCH * HEADS), 128, SM_AV>>>(
        ah, nullptr, kvh + INNER, kvl + INNER, nullptr, mh, nullptr, nullptr,
        NSEQ, NSEQ, 2 * INNER, INNER,
        (long long)HEADS * NSEQ * NSEQ, (long long)NSEQ * NSEQ,
        (long long)NSEQ * 2 * INNER, DHEAD,
        (long long)NSEQ * INNER, DHEAD, 1.f);

    // 6) out = mid @ Wo + bo -> f32             (2-term)
    mma_gemm<128,8,true,2,1,2><<<dim3(8, 32, 1), 256, SM_OUT>>>(
        mh, nullptr, woh, wol, out, nullptr, nullptr, bo,
        INNER, INNER, DIM, DIM, 0, 0, 0, 0, 0, 0, 1.f);
}